// round 3
// baseline (speedup 1.0000x reference)
#include <cuda_runtime.h>
#include <math.h>

// Problem constants
#define B_  4
#define T_  2048
#define H_  16
#define D_  64
#define C_  1024
#define FF_ 4096
#define M_  (B_ * T_)   // 8192 rows

// ---------------------------------------------------------------------------
// Scratch (device globals — no runtime allocation allowed)
// ---------------------------------------------------------------------------
__device__ float g_xn [M_ * C_];        // LN output (reused for LN1 and LN2)
__device__ float g_qkv[M_ * 3 * C_];    // qkv projections
__device__ float g_y  [M_ * C_];        // attention output
__device__ float g_x1 [M_ * C_];        // x + attn proj (first residual)
__device__ float g_h  [M_ * FF_];       // gelu(fc) activations

// ---------------------------------------------------------------------------
// LayerNorm: one block per row, 256 threads, C=1024 (4 floats / thread)
// ---------------------------------------------------------------------------
__global__ void __launch_bounds__(256) ln_kernel(
    const float* __restrict__ x, const float* __restrict__ w,
    const float* __restrict__ b, float* __restrict__ out)
{
    const int row = blockIdx.x;
    const int tid = threadIdx.x;
    const float4 v = ((const float4*)(x + (size_t)row * C_))[tid];

    float s  = v.x + v.y + v.z + v.w;
    float s2 = v.x*v.x + v.y*v.y + v.z*v.z + v.w*v.w;

    #pragma unroll
    for (int o = 16; o > 0; o >>= 1) {
        s  += __shfl_xor_sync(0xffffffffu, s,  o);
        s2 += __shfl_xor_sync(0xffffffffu, s2, o);
    }

    __shared__ float red[18];
    const int warp = tid >> 5, lane = tid & 31;
    if (lane == 0) { red[warp] = s; red[8 + warp] = s2; }
    __syncthreads();
    if (warp == 0) {
        float a  = (lane < 8) ? red[lane]     : 0.f;
        float a2 = (lane < 8) ? red[8 + lane] : 0.f;
        #pragma unroll
        for (int o = 4; o > 0; o >>= 1) {
            a  += __shfl_xor_sync(0xffffffffu, a,  o);
            a2 += __shfl_xor_sync(0xffffffffu, a2, o);
        }
        if (lane == 0) { red[16] = a * (1.0f / C_); red[17] = a2 * (1.0f / C_); }
    }
    __syncthreads();

    const float mean = red[16];
    const float var  = red[17] - mean * mean;
    const float rstd = rsqrtf(var + 1e-5f);

    const float4 wv = ((const float4*)w)[tid];
    const float4 bv = ((const float4*)b)[tid];
    float4 o4;
    o4.x = (v.x - mean) * rstd * wv.x + bv.x;
    o4.y = (v.y - mean) * rstd * wv.y + bv.y;
    o4.z = (v.z - mean) * rstd * wv.z + bv.z;
    o4.w = (v.w - mean) * rstd * wv.w + bv.w;
    ((float4*)(out + (size_t)row * C_))[tid] = o4;
}

// ---------------------------------------------------------------------------
// Exact GELU (erf form, matching torch F.gelu default / jax approximate=False)
// ---------------------------------------------------------------------------
__device__ __forceinline__ float gelu_exact(float x) {
    return 0.5f * x * (1.0f + erff(x * 0.70710678118654752f));
}

// ---------------------------------------------------------------------------
// SGEMM: out[M,N] = A[M,K] @ W[K,N] + bias[N]  (+ optional GELU / residual)
// 128x128 block tile, BK=16, 256 threads, 8x8 micro-tile per thread.
// All dims are multiples of tile sizes for this problem — no bounds checks.
// ---------------------------------------------------------------------------
template<int ACT, int RES>
__global__ void __launch_bounds__(256, 2) sgemm_kernel(
    const float* __restrict__ A, const float* __restrict__ W,
    const float* __restrict__ bias, const float* __restrict__ res,
    float* __restrict__ out, int M, int N, int K)
{
    constexpr int BM = 128, BN = 128, BK = 16;
    __shared__ float As[BK][BM + 4];   // padded: conflict-free transposed stores
    __shared__ float Bs[BK][BN];

    const int tid = threadIdx.x;
    const int bm  = blockIdx.y;
    const int bn  = blockIdx.x;
    const int tm  = (tid >> 4) << 3;   // 0..120
    const int tn  = (tid & 15) << 3;   // 0..120

    float acc[8][8];
    #pragma unroll
    for (int i = 0; i < 8; i++)
        #pragma unroll
        for (int j = 0; j < 8; j++) acc[i][j] = 0.f;

    const float* Aptr = A + (size_t)bm * BM * K;
    const float* Bptr = W + (size_t)bn * BN;

    // per-thread load coordinates
    const int ar = tid >> 1;           // A row 0..127
    const int ac = (tid & 1) * 8;      // A col group: 0 or 8
    const int br = tid >> 4;           // B row 0..15
    const int bc = (tid & 15) * 8;     // B col 0..120

    for (int k0 = 0; k0 < K; k0 += BK) {
        // load A tile (transposed into SMEM)
        {
            const float* ap = Aptr + (size_t)ar * K + k0 + ac;
            float4 t0 = *(const float4*)(ap);
            float4 t1 = *(const float4*)(ap + 4);
            As[ac + 0][ar] = t0.x; As[ac + 1][ar] = t0.y;
            As[ac + 2][ar] = t0.z; As[ac + 3][ar] = t0.w;
            As[ac + 4][ar] = t1.x; As[ac + 5][ar] = t1.y;
            As[ac + 6][ar] = t1.z; As[ac + 7][ar] = t1.w;
        }
        // load B tile
        {
            const float* bp = Bptr + (size_t)(k0 + br) * N + bc;
            *(float4*)&Bs[br][bc]     = *(const float4*)(bp);
            *(float4*)&Bs[br][bc + 4] = *(const float4*)(bp + 4);
        }
        __syncthreads();

        #pragma unroll
        for (int kk = 0; kk < BK; kk++) {
            float ra[8], rb[8];
            #pragma unroll
            for (int i = 0; i < 8; i++) ra[i] = As[kk][tm + i];
            #pragma unroll
            for (int j = 0; j < 8; j++) rb[j] = Bs[kk][tn + j];
            #pragma unroll
            for (int i = 0; i < 8; i++)
                #pragma unroll
                for (int j = 0; j < 8; j++)
                    acc[i][j] += ra[i] * rb[j];
        }
        __syncthreads();
    }

    // epilogue
    const int colbase = bn * BN + tn;
    float bb[8];
    #pragma unroll
    for (int j = 0; j < 8; j++) bb[j] = bias[colbase + j];

    #pragma unroll
    for (int i = 0; i < 8; i++) {
        const size_t row = (size_t)(bm * BM + tm + i);
        float* op = out + row * N + colbase;
        float vals[8];
        #pragma unroll
        for (int j = 0; j < 8; j++) {
            float v = acc[i][j] + bb[j];
            if (ACT == 1) v = gelu_exact(v);
            vals[j] = v;
        }
        if (RES) {
            const float* rp = res + row * N + colbase;
            float4 r0 = *(const float4*)(rp);
            float4 r1 = *(const float4*)(rp + 4);
            vals[0] += r0.x; vals[1] += r0.y; vals[2] += r0.z; vals[3] += r0.w;
            vals[4] += r1.x; vals[5] += r1.y; vals[6] += r1.z; vals[7] += r1.w;
        }
        *(float4*)(op)     = make_float4(vals[0], vals[1], vals[2], vals[3]);
        *(float4*)(op + 4) = make_float4(vals[4], vals[5], vals[6], vals[7]);
    }
}

// ---------------------------------------------------------------------------
// Causal flash attention, fp32. One thread = one query row (D=64).
// Block: 64 threads = 64 queries. Tiles of 64 keys in SMEM (padded rows).
// Grid: (T/64, H, B).
// ---------------------------------------------------------------------------
__global__ void __launch_bounds__(64) attn_kernel(
    const float* __restrict__ qkv, float* __restrict__ y)
{
    const int qt  = blockIdx.x;   // query tile
    const int h   = blockIdx.y;
    const int b   = blockIdx.z;
    const int tid = threadIdx.x;
    const int qi  = qt * 64 + tid;          // query index in [0, T)

    __shared__ float Ks[64][68];            // 68: pad so row-stores avoid 32-way conflicts
    __shared__ float Vs[64][68];

    // load q into registers
    float q[64];
    {
        const float* qp = qkv + ((size_t)(b * T_ + qi) * (3 * C_)) + h * D_;
        #pragma unroll
        for (int i = 0; i < 16; i++) {
            float4 t = ((const float4*)qp)[i];
            q[4*i+0] = t.x; q[4*i+1] = t.y; q[4*i+2] = t.z; q[4*i+3] = t.w;
        }
    }

    float o[64];
    #pragma unroll
    for (int d = 0; d < 64; d++) o[d] = 0.f;
    float m = -INFINITY, l = 0.f;

    for (int kt = 0; kt <= qt; kt++) {
        __syncthreads();
        // cooperative coalesced load of K and V tiles (64 rows x 64 floats)
        #pragma unroll
        for (int it = 0; it < 16; it++) {
            const int idx = it * 64 + tid;
            const int r   = idx >> 4;       // key row in tile
            const int c4  = idx & 15;       // float4 within row
            const size_t gbase = (size_t)(b * T_ + kt * 64 + r) * (3 * C_) + h * D_;
            ((float4*)&Ks[r][0])[c4] = ((const float4*)(qkv + gbase + C_))[c4];
            ((float4*)&Vs[r][0])[c4] = ((const float4*)(qkv + gbase + 2 * C_))[c4];
        }
        __syncthreads();

        const bool diag = (kt == qt);
        float s[64];
        float mnew = m;
        #pragma unroll
        for (int j = 0; j < 64; j++) {
            float acc = 0.f;
            #pragma unroll
            for (int d = 0; d < 64; d += 4) {
                float4 kv = *(const float4*)&Ks[j][d];
                acc += q[d]   * kv.x + q[d+1] * kv.y
                     + q[d+2] * kv.z + q[d+3] * kv.w;
            }
            float sv = acc * 0.125f;                    // 1/sqrt(64)
            if (diag && j > tid) sv = -INFINITY;        // causal mask
            s[j] = sv;
            mnew = fmaxf(mnew, sv);
        }

        const float corr = __expf(m - mnew);            // 0 when m == -inf
        l *= corr;
        #pragma unroll
        for (int d = 0; d < 64; d++) o[d] *= corr;

        #pragma unroll
        for (int j = 0; j < 64; j++) {
            const float p = __expf(s[j] - mnew);        // 0 for masked entries
            l += p;
            #pragma unroll
            for (int d = 0; d < 64; d += 4) {
                float4 vv = *(const float4*)&Vs[j][d];
                o[d]   += p * vv.x;  o[d+1] += p * vv.y;
                o[d+2] += p * vv.z;  o[d+3] += p * vv.w;
            }
        }
        m = mnew;
    }

    const float inv = 1.f / l;
    float* yp = y + (size_t)(b * T_ + qi) * C_ + h * D_;
    #pragma unroll
    for (int i = 0; i < 16; i++) {
        float4 t;
        t.x = o[4*i+0] * inv; t.y = o[4*i+1] * inv;
        t.z = o[4*i+2] * inv; t.w = o[4*i+3] * inv;
        ((float4*)yp)[i] = t;
    }
}

// ---------------------------------------------------------------------------
// Launch
// ---------------------------------------------------------------------------
extern "C" void kernel_launch(void* const* d_in, const int* in_sizes, int n_in,
                              void* d_out, int out_size)
{
    (void)in_sizes; (void)n_in; (void)out_size;
    const float* x     = (const float*)d_in[0];
    const float* ln1_w = (const float*)d_in[1];
    const float* ln1_b = (const float*)d_in[2];
    const float* w_qkv = (const float*)d_in[3];
    const float* b_qkv = (const float*)d_in[4];
    const float* w_o   = (const float*)d_in[5];
    const float* b_o   = (const float*)d_in[6];
    const float* ln2_w = (const float*)d_in[7];
    const float* ln2_b = (const float*)d_in[8];
    const float* w_fc  = (const float*)d_in[9];
    const float* b_fc  = (const float*)d_in[10];
    const float* w_out = (const float*)d_in[11];
    const float* b_out = (const float*)d_in[12];
    float* out = (float*)d_out;

    float *xn, *qkv, *y, *x1, *hbuf;
    cudaGetSymbolAddress((void**)&xn,   g_xn);
    cudaGetSymbolAddress((void**)&qkv,  g_qkv);
    cudaGetSymbolAddress((void**)&y,    g_y);
    cudaGetSymbolAddress((void**)&x1,   g_x1);
    cudaGetSymbolAddress((void**)&hbuf, g_h);

    // 1) LN1
    ln_kernel<<<M_, 256>>>(x, ln1_w, ln1_b, xn);
    // 2) qkv = xn @ w_qkv + b_qkv                       [8192 x 3072]
    sgemm_kernel<0,0><<<dim3(3 * C_ / 128, M_ / 128), 256>>>(
        xn, w_qkv, b_qkv, nullptr, qkv, M_, 3 * C_, C_);
    // 3) causal attention -> y                          [8192 x 1024]
    attn_kernel<<<dim3(T_ / 64, H_, B_), 64>>>(qkv, y);
    // 4) x1 = x + y @ w_o + b_o
    sgemm_kernel<0,1><<<dim3(C_ / 128, M_ / 128), 256>>>(
        y, w_o, b_o, x, x1, M_, C_, C_);
    // 5) LN2 (reuse xn buffer)
    ln_kernel<<<M_, 256>>>(x1, ln2_w, ln2_b, xn);
    // 6) h = gelu(xn @ w_fc + b_fc)                     [8192 x 4096]
    sgemm_kernel<1,0><<<dim3(FF_ / 128, M_ / 128), 256>>>(
        xn, w_fc, b_fc, nullptr, hbuf, M_, FF_, C_);
    // 7) out = x1 + h @ w_out + b_out
    sgemm_kernel<0,1><<<dim3(C_ / 128, M_ / 128), 256>>>(
        hbuf, w_out, b_out, x1, out, M_, C_, FF_);
}

// round 4
// speedup vs baseline: 1.7884x; 1.7884x over previous
#include <cuda_runtime.h>
#include <math.h>
#include <stdint.h>

// Problem constants
#define B_  4
#define T_  2048
#define H_  16
#define D_  64
#define C_  1024
#define FF_ 4096
#define M_  (B_ * T_)   // 8192 rows

// ---------------------------------------------------------------------------
// Scratch (device globals — no runtime allocation allowed)
// ---------------------------------------------------------------------------
__device__ float g_xn [M_ * C_];        // LN output (reused for LN1 and LN2)
__device__ float g_qkv[M_ * 3 * C_];    // qkv projections
__device__ float g_y  [M_ * C_];        // attention output
__device__ float g_x1 [M_ * C_];        // x + attn proj (first residual)
__device__ float g_h  [M_ * FF_];       // gelu(fc) activations

// ---------------------------------------------------------------------------
// LayerNorm: one block per row, 256 threads, C=1024 (4 floats / thread)
// ---------------------------------------------------------------------------
__global__ void __launch_bounds__(256) ln_kernel(
    const float* __restrict__ x, const float* __restrict__ w,
    const float* __restrict__ b, float* __restrict__ out)
{
    const int row = blockIdx.x;
    const int tid = threadIdx.x;
    const float4 v = ((const float4*)(x + (size_t)row * C_))[tid];

    float s  = v.x + v.y + v.z + v.w;
    float s2 = v.x*v.x + v.y*v.y + v.z*v.z + v.w*v.w;

    #pragma unroll
    for (int o = 16; o > 0; o >>= 1) {
        s  += __shfl_xor_sync(0xffffffffu, s,  o);
        s2 += __shfl_xor_sync(0xffffffffu, s2, o);
    }

    __shared__ float red[18];
    const int warp = tid >> 5, lane = tid & 31;
    if (lane == 0) { red[warp] = s; red[8 + warp] = s2; }
    __syncthreads();
    if (warp == 0) {
        float a  = (lane < 8) ? red[lane]     : 0.f;
        float a2 = (lane < 8) ? red[8 + lane] : 0.f;
        #pragma unroll
        for (int o = 4; o > 0; o >>= 1) {
            a  += __shfl_xor_sync(0xffffffffu, a,  o);
            a2 += __shfl_xor_sync(0xffffffffu, a2, o);
        }
        if (lane == 0) { red[16] = a * (1.0f / C_); red[17] = a2 * (1.0f / C_); }
    }
    __syncthreads();

    const float mean = red[16];
    const float var  = red[17] - mean * mean;
    const float rstd = rsqrtf(var + 1e-5f);

    const float4 wv = ((const float4*)w)[tid];
    const float4 bv = ((const float4*)b)[tid];
    float4 o4;
    o4.x = (v.x - mean) * rstd * wv.x + bv.x;
    o4.y = (v.y - mean) * rstd * wv.y + bv.y;
    o4.z = (v.z - mean) * rstd * wv.z + bv.z;
    o4.w = (v.w - mean) * rstd * wv.w + bv.w;
    ((float4*)(out + (size_t)row * C_))[tid] = o4;
}

// ---------------------------------------------------------------------------
// Exact GELU (erf form)
// ---------------------------------------------------------------------------
__device__ __forceinline__ float gelu_exact(float x) {
    return 0.5f * x * (1.0f + erff(x * 0.70710678118654752f));
}

// ---------------------------------------------------------------------------
// TF32 tensor-core GEMM: out[M,N] = A[M,K] @ W[K,N] + bias (+GELU / +residual)
// 128x128x32 CTA tile, 8 warps (2x4), each warp 64x32 via m16n8k8 tf32 mma.
// Double-buffered cp.async. fp32 accumulation.
// ---------------------------------------------------------------------------
#define BM 128
#define BN 128
#define BK 32
#define A_STRIDE 36   // 36 % 32 == 4 -> conflict-free A fragment loads
#define B_STRIDE 136  // 136 % 32 == 8 -> conflict-free B fragment loads
#define A_TILE_FLOATS (BM * A_STRIDE)   // 4608
#define B_TILE_FLOATS (BK * B_STRIDE)   // 4352
#define SMEM_BYTES ((2 * A_TILE_FLOATS + 2 * B_TILE_FLOATS) * 4)  // 71680

__device__ __forceinline__ uint32_t f2tf32(float f) {
    uint32_t r;
    asm("cvt.rna.tf32.f32 %0, %1;" : "=r"(r) : "f"(f));
    return r;
}

__device__ __forceinline__ void mma_tf32(
    float& d0, float& d1, float& d2, float& d3,
    uint32_t a0, uint32_t a1, uint32_t a2, uint32_t a3,
    uint32_t b0, uint32_t b1)
{
    asm volatile(
        "mma.sync.aligned.m16n8k8.row.col.f32.tf32.tf32.f32 "
        "{%0,%1,%2,%3}, {%4,%5,%6,%7}, {%8,%9}, {%0,%1,%2,%3};\n"
        : "+f"(d0), "+f"(d1), "+f"(d2), "+f"(d3)
        : "r"(a0), "r"(a1), "r"(a2), "r"(a3), "r"(b0), "r"(b1));
}

__device__ __forceinline__ void cp_async16(void* dst_smem, const void* src) {
    uint32_t d = (uint32_t)__cvta_generic_to_shared(dst_smem);
    asm volatile("cp.async.cg.shared.global [%0], [%1], 16;\n" :: "r"(d), "l"(src));
}
__device__ __forceinline__ void cp_commit() {
    asm volatile("cp.async.commit_group;\n");
}
template<int N>
__device__ __forceinline__ void cp_wait() {
    asm volatile("cp.async.wait_group %0;\n" :: "n"(N));
}

template<int ACT, int RES>
__global__ void __launch_bounds__(256, 2) gemm_tc_kernel(
    const float* __restrict__ A, const float* __restrict__ W,
    const float* __restrict__ bias, const float* __restrict__ res,
    float* __restrict__ out, int M, int N, int K)
{
    extern __shared__ float smem[];
    float* As = smem;                         // 2 buffers of A_TILE_FLOATS
    float* Bs = smem + 2 * A_TILE_FLOATS;     // 2 buffers of B_TILE_FLOATS

    const int tid  = threadIdx.x;
    const int lane = tid & 31;
    const int wid  = tid >> 5;
    const int wm   = wid >> 2;                // 0..1 : warp row (64 rows each)
    const int wn   = wid & 3;                 // 0..3 : warp col (32 cols each)
    const int bm   = blockIdx.y;
    const int bn   = blockIdx.x;

    // Global load coordinates (per-thread, float4 granularity)
    // A tile: 128 rows x 32 floats = 1024 float4, 4 iters x 256 threads
    // B tile:  32 rows x 128 floats = 1024 float4
    const int a_row0 = tid >> 1;              // with iter stride: idx>>3
    (void)a_row0;

    float acc[4][4][4];
    #pragma unroll
    for (int i = 0; i < 4; i++)
        #pragma unroll
        for (int j = 0; j < 4; j++)
            #pragma unroll
            for (int r = 0; r < 4; r++) acc[i][j][r] = 0.f;

    const int ntiles = K / BK;

    // ---- async tile loader ----
    auto load_tile = [&](int t, int buf) {
        const int k0 = t * BK;
        float* Ab = As + buf * A_TILE_FLOATS;
        float* Bb = Bs + buf * B_TILE_FLOATS;
        #pragma unroll
        for (int i = 0; i < 4; i++) {
            const int idx = i * 256 + tid;
            { // A
                const int row = idx >> 3, c4 = idx & 7;
                cp_async16(Ab + row * A_STRIDE + c4 * 4,
                           A + (size_t)(bm * BM + row) * K + k0 + c4 * 4);
            }
            { // B
                const int row = idx >> 5, c4 = idx & 31;
                cp_async16(Bb + row * B_STRIDE + c4 * 4,
                           W + (size_t)(k0 + row) * N + bn * BN + c4 * 4);
            }
        }
        cp_commit();
    };

    load_tile(0, 0);

    const int fr = lane >> 2;   // 0..7
    const int fc = lane & 3;    // 0..3

    int buf = 0;
    for (int t = 0; t < ntiles; t++) {
        if (t + 1 < ntiles) {
            load_tile(t + 1, buf ^ 1);
            cp_wait<1>();
        } else {
            cp_wait<0>();
        }
        __syncthreads();

        const float* Ab = As + buf * A_TILE_FLOATS;
        const float* Bb = Bs + buf * B_TILE_FLOATS;

        #pragma unroll
        for (int kk = 0; kk < 4; kk++) {
            const int kb = kk * 8;
            uint32_t af[4][4], bf[4][2];
            #pragma unroll
            for (int mi = 0; mi < 4; mi++) {
                const int rb = wm * 64 + mi * 16;
                af[mi][0] = f2tf32(Ab[(rb + fr    ) * A_STRIDE + kb + fc    ]);
                af[mi][1] = f2tf32(Ab[(rb + fr + 8) * A_STRIDE + kb + fc    ]);
                af[mi][2] = f2tf32(Ab[(rb + fr    ) * A_STRIDE + kb + fc + 4]);
                af[mi][3] = f2tf32(Ab[(rb + fr + 8) * A_STRIDE + kb + fc + 4]);
            }
            #pragma unroll
            for (int ni = 0; ni < 4; ni++) {
                const int cb = wn * 32 + ni * 8 + fr;
                bf[ni][0] = f2tf32(Bb[(kb + fc    ) * B_STRIDE + cb]);
                bf[ni][1] = f2tf32(Bb[(kb + fc + 4) * B_STRIDE + cb]);
            }
            #pragma unroll
            for (int mi = 0; mi < 4; mi++)
                #pragma unroll
                for (int ni = 0; ni < 4; ni++)
                    mma_tf32(acc[mi][ni][0], acc[mi][ni][1],
                             acc[mi][ni][2], acc[mi][ni][3],
                             af[mi][0], af[mi][1], af[mi][2], af[mi][3],
                             bf[ni][0], bf[ni][1]);
        }
        __syncthreads();
        buf ^= 1;
    }

    // ---- epilogue ----
    #pragma unroll
    for (int mi = 0; mi < 4; mi++) {
        const int row0 = bm * BM + wm * 64 + mi * 16 + fr;
        #pragma unroll
        for (int ni = 0; ni < 4; ni++) {
            const int col = bn * BN + wn * 32 + ni * 8 + fc * 2;
            const float b0 = bias[col], b1 = bias[col + 1];

            float v0 = acc[mi][ni][0] + b0;
            float v1 = acc[mi][ni][1] + b1;
            float v2 = acc[mi][ni][2] + b0;
            float v3 = acc[mi][ni][3] + b1;
            if (ACT == 1) {
                v0 = gelu_exact(v0); v1 = gelu_exact(v1);
                v2 = gelu_exact(v2); v3 = gelu_exact(v3);
            }
            if (RES) {
                const float2 r0 = *(const float2*)(res + (size_t)row0 * N + col);
                const float2 r1 = *(const float2*)(res + (size_t)(row0 + 8) * N + col);
                v0 += r0.x; v1 += r0.y; v2 += r1.x; v3 += r1.y;
            }
            *(float2*)(out + (size_t)row0 * N + col)       = make_float2(v0, v1);
            *(float2*)(out + (size_t)(row0 + 8) * N + col) = make_float2(v2, v3);
        }
    }
}

// ---------------------------------------------------------------------------
// Causal flash attention, fp32. One thread = one query row (D=64).
// ---------------------------------------------------------------------------
__global__ void __launch_bounds__(64) attn_kernel(
    const float* __restrict__ qkv, float* __restrict__ y)
{
    const int qt  = blockIdx.x;
    const int h   = blockIdx.y;
    const int b   = blockIdx.z;
    const int tid = threadIdx.x;
    const int qi  = qt * 64 + tid;

    __shared__ float Ks[64][68];
    __shared__ float Vs[64][68];

    float q[64];
    {
        const float* qp = qkv + ((size_t)(b * T_ + qi) * (3 * C_)) + h * D_;
        #pragma unroll
        for (int i = 0; i < 16; i++) {
            float4 t = ((const float4*)qp)[i];
            q[4*i+0] = t.x; q[4*i+1] = t.y; q[4*i+2] = t.z; q[4*i+3] = t.w;
        }
    }

    float o[64];
    #pragma unroll
    for (int d = 0; d < 64; d++) o[d] = 0.f;
    float m = -INFINITY, l = 0.f;

    for (int kt = 0; kt <= qt; kt++) {
        __syncthreads();
        #pragma unroll
        for (int it = 0; it < 16; it++) {
            const int idx = it * 64 + tid;
            const int r   = idx >> 4;
            const int c4  = idx & 15;
            const size_t gbase = (size_t)(b * T_ + kt * 64 + r) * (3 * C_) + h * D_;
            ((float4*)&Ks[r][0])[c4] = ((const float4*)(qkv + gbase + C_))[c4];
            ((float4*)&Vs[r][0])[c4] = ((const float4*)(qkv + gbase + 2 * C_))[c4];
        }
        __syncthreads();

        const bool diag = (kt == qt);
        float s[64];
        float mnew = m;
        #pragma unroll
        for (int j = 0; j < 64; j++) {
            float acc = 0.f;
            #pragma unroll
            for (int d = 0; d < 64; d += 4) {
                float4 kv = *(const float4*)&Ks[j][d];
                acc += q[d]   * kv.x + q[d+1] * kv.y
                     + q[d+2] * kv.z + q[d+3] * kv.w;
            }
            float sv = acc * 0.125f;
            if (diag && j > tid) sv = -INFINITY;
            s[j] = sv;
            mnew = fmaxf(mnew, sv);
        }

        const float corr = __expf(m - mnew);
        l *= corr;
        #pragma unroll
        for (int d = 0; d < 64; d++) o[d] *= corr;

        #pragma unroll
        for (int j = 0; j < 64; j++) {
            const float p = __expf(s[j] - mnew);
            l += p;
            #pragma unroll
            for (int d = 0; d < 64; d += 4) {
                float4 vv = *(const float4*)&Vs[j][d];
                o[d]   += p * vv.x;  o[d+1] += p * vv.y;
                o[d+2] += p * vv.z;  o[d+3] += p * vv.w;
            }
        }
        m = mnew;
    }

    const float inv = 1.f / l;
    float* yp = y + (size_t)(b * T_ + qi) * C_ + h * D_;
    #pragma unroll
    for (int i = 0; i < 16; i++) {
        float4 t;
        t.x = o[4*i+0] * inv; t.y = o[4*i+1] * inv;
        t.z = o[4*i+2] * inv; t.w = o[4*i+3] * inv;
        ((float4*)yp)[i] = t;
    }
}

// ---------------------------------------------------------------------------
// Launch
// ---------------------------------------------------------------------------
extern "C" void kernel_launch(void* const* d_in, const int* in_sizes, int n_in,
                              void* d_out, int out_size)
{
    (void)in_sizes; (void)n_in; (void)out_size;
    const float* x     = (const float*)d_in[0];
    const float* ln1_w = (const float*)d_in[1];
    const float* ln1_b = (const float*)d_in[2];
    const float* w_qkv = (const float*)d_in[3];
    const float* b_qkv = (const float*)d_in[4];
    const float* w_o   = (const float*)d_in[5];
    const float* b_o   = (const float*)d_in[6];
    const float* ln2_w = (const float*)d_in[7];
    const float* ln2_b = (const float*)d_in[8];
    const float* w_fc  = (const float*)d_in[9];
    const float* b_fc  = (const float*)d_in[10];
    const float* w_out = (const float*)d_in[11];
    const float* b_out = (const float*)d_in[12];
    float* out = (float*)d_out;

    float *xn, *qkv, *y, *x1, *hbuf;
    cudaGetSymbolAddress((void**)&xn,   g_xn);
    cudaGetSymbolAddress((void**)&qkv,  g_qkv);
    cudaGetSymbolAddress((void**)&y,    g_y);
    cudaGetSymbolAddress((void**)&x1,   g_x1);
    cudaGetSymbolAddress((void**)&hbuf, g_h);

    // Opt-in to >48KB dynamic smem (attribute set, not an allocation)
    cudaFuncSetAttribute(gemm_tc_kernel<0,0>,
        cudaFuncAttributeMaxDynamicSharedMemorySize, SMEM_BYTES);
    cudaFuncSetAttribute(gemm_tc_kernel<0,1>,
        cudaFuncAttributeMaxDynamicSharedMemorySize, SMEM_BYTES);
    cudaFuncSetAttribute(gemm_tc_kernel<1,0>,
        cudaFuncAttributeMaxDynamicSharedMemorySize, SMEM_BYTES);

    // 1) LN1
    ln_kernel<<<M_, 256>>>(x, ln1_w, ln1_b, xn);
    // 2) qkv = xn @ w_qkv + b_qkv                       [8192 x 3072]
    gemm_tc_kernel<0,0><<<dim3(3 * C_ / BN, M_ / BM), 256, SMEM_BYTES>>>(
        xn, w_qkv, b_qkv, nullptr, qkv, M_, 3 * C_, C_);
    // 3) causal attention -> y                          [8192 x 1024]
    attn_kernel<<<dim3(T_ / 64, H_, B_), 64>>>(qkv, y);
    // 4) x1 = x + y @ w_o + b_o
    gemm_tc_kernel<0,1><<<dim3(C_ / BN, M_ / BM), 256, SMEM_BYTES>>>(
        y, w_o, b_o, x, x1, M_, C_, C_);
    // 5) LN2 (reuse xn buffer)
    ln_kernel<<<M_, 256>>>(x1, ln2_w, ln2_b, xn);
    // 6) h = gelu(xn @ w_fc + b_fc)                     [8192 x 4096]
    gemm_tc_kernel<1,0><<<dim3(FF_ / BN, M_ / BM), 256, SMEM_BYTES>>>(
        xn, w_fc, b_fc, nullptr, hbuf, M_, FF_, C_);
    // 7) out = x1 + h @ w_out + b_out
    gemm_tc_kernel<0,1><<<dim3(C_ / BN, M_ / BM), 256, SMEM_BYTES>>>(
        hbuf, w_out, b_out, x1, out, M_, C_, FF_);
}

// round 5
// speedup vs baseline: 4.3568x; 2.4361x over previous
#include <cuda_runtime.h>
#include <math.h>
#include <stdint.h>

// Problem constants
#define B_  4
#define T_  2048
#define H_  16
#define D_  64
#define C_  1024
#define FF_ 4096
#define M_  (B_ * T_)   // 8192 rows

// ---------------------------------------------------------------------------
// Scratch (device globals — no runtime allocation allowed)
// ---------------------------------------------------------------------------
__device__ float g_xn [M_ * C_];
__device__ float g_qkv[M_ * 3 * C_];
__device__ float g_y  [M_ * C_];
__device__ float g_x1 [M_ * C_];
__device__ float g_h  [M_ * FF_];

// ---------------------------------------------------------------------------
// Helpers
// ---------------------------------------------------------------------------
__device__ __forceinline__ uint32_t f2tf32(float f) {
    uint32_t r;
    asm("cvt.rna.tf32.f32 %0, %1;" : "=r"(r) : "f"(f));
    return r;
}
__device__ __forceinline__ float tf32_round(float f) {
    return __uint_as_float(f2tf32(f));
}

__device__ __forceinline__ void mma_tf32(
    float& d0, float& d1, float& d2, float& d3,
    uint32_t a0, uint32_t a1, uint32_t a2, uint32_t a3,
    uint32_t b0, uint32_t b1)
{
    asm volatile(
        "mma.sync.aligned.m16n8k8.row.col.f32.tf32.tf32.f32 "
        "{%0,%1,%2,%3}, {%4,%5,%6,%7}, {%8,%9}, {%0,%1,%2,%3};\n"
        : "+f"(d0), "+f"(d1), "+f"(d2), "+f"(d3)
        : "r"(a0), "r"(a1), "r"(a2), "r"(a3), "r"(b0), "r"(b1));
}

__device__ __forceinline__ void cp_async16(void* dst_smem, const void* src) {
    uint32_t d = (uint32_t)__cvta_generic_to_shared(dst_smem);
    asm volatile("cp.async.cg.shared.global [%0], [%1], 16;\n" :: "r"(d), "l"(src));
}
__device__ __forceinline__ void cp_commit() {
    asm volatile("cp.async.commit_group;\n");
}
template<int N>
__device__ __forceinline__ void cp_wait() {
    asm volatile("cp.async.wait_group %0;\n" :: "n"(N));
}

__device__ __forceinline__ float gelu_exact(float x) {
    return 0.5f * x * (1.0f + erff(x * 0.70710678118654752f));
}

// ---------------------------------------------------------------------------
// LayerNorm
// ---------------------------------------------------------------------------
__global__ void __launch_bounds__(256) ln_kernel(
    const float* __restrict__ x, const float* __restrict__ w,
    const float* __restrict__ b, float* __restrict__ out)
{
    const int row = blockIdx.x;
    const int tid = threadIdx.x;
    const float4 v = ((const float4*)(x + (size_t)row * C_))[tid];

    float s  = v.x + v.y + v.z + v.w;
    float s2 = v.x*v.x + v.y*v.y + v.z*v.z + v.w*v.w;

    #pragma unroll
    for (int o = 16; o > 0; o >>= 1) {
        s  += __shfl_xor_sync(0xffffffffu, s,  o);
        s2 += __shfl_xor_sync(0xffffffffu, s2, o);
    }

    __shared__ float red[18];
    const int warp = tid >> 5, lane = tid & 31;
    if (lane == 0) { red[warp] = s; red[8 + warp] = s2; }
    __syncthreads();
    if (warp == 0) {
        float a  = (lane < 8) ? red[lane]     : 0.f;
        float a2 = (lane < 8) ? red[8 + lane] : 0.f;
        #pragma unroll
        for (int o = 4; o > 0; o >>= 1) {
            a  += __shfl_xor_sync(0xffffffffu, a,  o);
            a2 += __shfl_xor_sync(0xffffffffu, a2, o);
        }
        if (lane == 0) { red[16] = a * (1.0f / C_); red[17] = a2 * (1.0f / C_); }
    }
    __syncthreads();

    const float mean = red[16];
    const float var  = red[17] - mean * mean;
    const float rstd = rsqrtf(var + 1e-5f);

    const float4 wv = ((const float4*)w)[tid];
    const float4 bv = ((const float4*)b)[tid];
    float4 o4;
    o4.x = (v.x - mean) * rstd * wv.x + bv.x;
    o4.y = (v.y - mean) * rstd * wv.y + bv.y;
    o4.z = (v.z - mean) * rstd * wv.z + bv.z;
    o4.w = (v.w - mean) * rstd * wv.w + bv.w;
    ((float4*)(out + (size_t)row * C_))[tid] = o4;
}

// ---------------------------------------------------------------------------
// TF32 tensor-core GEMM (as R4), plus CVT: store tf32-rounded outputs
// ---------------------------------------------------------------------------
#define BM 128
#define BN 128
#define BK 32
#define A_STRIDE 36
#define B_STRIDE 136
#define A_TILE_FLOATS (BM * A_STRIDE)
#define B_TILE_FLOATS (BK * B_STRIDE)
#define SMEM_BYTES ((2 * A_TILE_FLOATS + 2 * B_TILE_FLOATS) * 4)

template<int ACT, int RES, int CVT>
__global__ void __launch_bounds__(256, 2) gemm_tc_kernel(
    const float* __restrict__ A, const float* __restrict__ W,
    const float* __restrict__ bias, const float* __restrict__ res,
    float* __restrict__ out, int M, int N, int K)
{
    extern __shared__ float smem[];
    float* As = smem;
    float* Bs = smem + 2 * A_TILE_FLOATS;

    const int tid  = threadIdx.x;
    const int lane = tid & 31;
    const int wid  = tid >> 5;
    const int wm   = wid >> 2;
    const int wn   = wid & 3;
    const int bm   = blockIdx.y;
    const int bn   = blockIdx.x;

    float acc[4][4][4];
    #pragma unroll
    for (int i = 0; i < 4; i++)
        #pragma unroll
        for (int j = 0; j < 4; j++)
            #pragma unroll
            for (int r = 0; r < 4; r++) acc[i][j][r] = 0.f;

    const int ntiles = K / BK;

    auto load_tile = [&](int t, int buf) {
        const int k0 = t * BK;
        float* Ab = As + buf * A_TILE_FLOATS;
        float* Bb = Bs + buf * B_TILE_FLOATS;
        #pragma unroll
        for (int i = 0; i < 4; i++) {
            const int idx = i * 256 + tid;
            {
                const int row = idx >> 3, c4 = idx & 7;
                cp_async16(Ab + row * A_STRIDE + c4 * 4,
                           A + (size_t)(bm * BM + row) * K + k0 + c4 * 4);
            }
            {
                const int row = idx >> 5, c4 = idx & 31;
                cp_async16(Bb + row * B_STRIDE + c4 * 4,
                           W + (size_t)(k0 + row) * N + bn * BN + c4 * 4);
            }
        }
        cp_commit();
    };

    load_tile(0, 0);

    const int fr = lane >> 2;
    const int fc = lane & 3;

    int buf = 0;
    for (int t = 0; t < ntiles; t++) {
        if (t + 1 < ntiles) {
            load_tile(t + 1, buf ^ 1);
            cp_wait<1>();
        } else {
            cp_wait<0>();
        }
        __syncthreads();

        const float* Ab = As + buf * A_TILE_FLOATS;
        const float* Bb = Bs + buf * B_TILE_FLOATS;

        #pragma unroll
        for (int kk = 0; kk < 4; kk++) {
            const int kb = kk * 8;
            uint32_t af[4][4], bf[4][2];
            #pragma unroll
            for (int mi = 0; mi < 4; mi++) {
                const int rb = wm * 64 + mi * 16;
                af[mi][0] = f2tf32(Ab[(rb + fr    ) * A_STRIDE + kb + fc    ]);
                af[mi][1] = f2tf32(Ab[(rb + fr + 8) * A_STRIDE + kb + fc    ]);
                af[mi][2] = f2tf32(Ab[(rb + fr    ) * A_STRIDE + kb + fc + 4]);
                af[mi][3] = f2tf32(Ab[(rb + fr + 8) * A_STRIDE + kb + fc + 4]);
            }
            #pragma unroll
            for (int ni = 0; ni < 4; ni++) {
                const int cb = wn * 32 + ni * 8 + fr;
                bf[ni][0] = f2tf32(Bb[(kb + fc    ) * B_STRIDE + cb]);
                bf[ni][1] = f2tf32(Bb[(kb + fc + 4) * B_STRIDE + cb]);
            }
            #pragma unroll
            for (int mi = 0; mi < 4; mi++)
                #pragma unroll
                for (int ni = 0; ni < 4; ni++)
                    mma_tf32(acc[mi][ni][0], acc[mi][ni][1],
                             acc[mi][ni][2], acc[mi][ni][3],
                             af[mi][0], af[mi][1], af[mi][2], af[mi][3],
                             bf[ni][0], bf[ni][1]);
        }
        __syncthreads();
        buf ^= 1;
    }

    #pragma unroll
    for (int mi = 0; mi < 4; mi++) {
        const int row0 = bm * BM + wm * 64 + mi * 16 + fr;
        #pragma unroll
        for (int ni = 0; ni < 4; ni++) {
            const int col = bn * BN + wn * 32 + ni * 8 + fc * 2;
            const float b0 = bias[col], b1 = bias[col + 1];

            float v0 = acc[mi][ni][0] + b0;
            float v1 = acc[mi][ni][1] + b1;
            float v2 = acc[mi][ni][2] + b0;
            float v3 = acc[mi][ni][3] + b1;
            if (ACT == 1) {
                v0 = gelu_exact(v0); v1 = gelu_exact(v1);
                v2 = gelu_exact(v2); v3 = gelu_exact(v3);
            }
            if (RES) {
                const float2 r0 = *(const float2*)(res + (size_t)row0 * N + col);
                const float2 r1 = *(const float2*)(res + (size_t)(row0 + 8) * N + col);
                v0 += r0.x; v1 += r0.y; v2 += r1.x; v3 += r1.y;
            }
            if (CVT) {
                v0 = tf32_round(v0); v1 = tf32_round(v1);
                v2 = tf32_round(v2); v3 = tf32_round(v3);
            }
            *(float2*)(out + (size_t)row0 * N + col)       = make_float2(v0, v1);
            *(float2*)(out + (size_t)(row0 + 8) * N + col) = make_float2(v2, v3);
        }
    }
}

// ---------------------------------------------------------------------------
// Tensor-core causal flash attention (tf32).
// CTA = 128 threads (4 warps) per (b, h, 64-query tile). Warp w owns rows
// [16w, 16w+16). K/V tiles of 64 keys, cp.async double-buffered.
// qkv buffer values are already tf32-rounded by the qkv GEMM epilogue.
// SMEM strides: Q/K/P = 68 (conflict-free frag loads), V = 72.
// ---------------------------------------------------------------------------
#define QS_STR 68
#define VS_STR 72
#define QS_FLOATS (64 * QS_STR)     // 4352
#define KS_FLOATS (64 * QS_STR)     // 4352 per buffer
#define VS_FLOATS (64 * VS_STR)     // 4608 per buffer
#define PS_FLOATS (64 * QS_STR)     // 4352 (4 warps x 16 rows)
#define ATTN_SMEM_BYTES ((QS_FLOATS + 2*KS_FLOATS + 2*VS_FLOATS + PS_FLOATS) * 4)

__global__ void __launch_bounds__(128) attn_tc_kernel(
    const float* __restrict__ qkv, float* __restrict__ y)
{
    extern __shared__ float sm[];
    float* Qs = sm;
    float* Ks = Qs + QS_FLOATS;
    float* Vs = Ks + 2 * KS_FLOATS;
    float* Ps = Vs + 2 * VS_FLOATS;

    const int qt   = blockIdx.x;
    const int h    = blockIdx.y;
    const int b    = blockIdx.z;
    const int tid  = threadIdx.x;
    const int lane = tid & 31;
    const int w    = tid >> 5;
    const int fr   = lane >> 2;
    const int fc   = lane & 3;

    const size_t base = (size_t)(b * T_) * (3 * C_) + h * D_;

    // ---- load Q tile (+ first K/V tile) in group 0 ----
    {
        #pragma unroll
        for (int i = 0; i < 8; i++) {
            const int idx = i * 128 + tid;      // 0..1023
            const int r = idx >> 4, c4 = idx & 15;
            const float* src = qkv + base + (size_t)(qt * 64 + r) * (3 * C_) + c4 * 4;
            cp_async16(Qs + r * QS_STR + c4 * 4, src);
        }
        #pragma unroll
        for (int i = 0; i < 8; i++) {
            const int idx = i * 128 + tid;
            const int r = idx >> 4, c4 = idx & 15;
            const float* src = qkv + base + (size_t)(r) * (3 * C_) + c4 * 4;  // kt = 0
            cp_async16(Ks + r * QS_STR + c4 * 4, src + C_);
            cp_async16(Vs + r * VS_STR + c4 * 4, src + 2 * C_);
        }
        cp_commit();
    }

    auto load_kv = [&](int kt, int bufi) {
        float* Kb = Ks + bufi * KS_FLOATS;
        float* Vb = Vs + bufi * VS_FLOATS;
        #pragma unroll
        for (int i = 0; i < 8; i++) {
            const int idx = i * 128 + tid;
            const int r = idx >> 4, c4 = idx & 15;
            const float* src = qkv + base + (size_t)(kt * 64 + r) * (3 * C_) + c4 * 4;
            cp_async16(Kb + r * QS_STR + c4 * 4, src + C_);
            cp_async16(Vb + r * VS_STR + c4 * 4, src + 2 * C_);
        }
        cp_commit();
    };

    float accO[8][4];
    #pragma unroll
    for (int ni = 0; ni < 8; ni++)
        #pragma unroll
        for (int r = 0; r < 4; r++) accO[ni][r] = 0.f;
    float m0 = -INFINITY, m1 = -INFINITY, l0 = 0.f, l1 = 0.f;

    float* Ps_w = Ps + w * 16 * QS_STR;
    const int rlo = w * 16 + fr;      // local query row (lo half)

    int buf = 0;
    for (int kt = 0; kt <= qt; kt++) {
        if (kt < qt) { load_kv(kt + 1, buf ^ 1); cp_wait<1>(); }
        else         { cp_wait<0>(); }
        __syncthreads();

        const float* Kb = Ks + buf * KS_FLOATS;
        const float* Vb = Vs + buf * VS_FLOATS;

        // ---- S = Q K^T (warp rows rlo, rlo+8 x 64 keys) ----
        float accS[8][4];
        #pragma unroll
        for (int ni = 0; ni < 8; ni++)
            #pragma unroll
            for (int r = 0; r < 4; r++) accS[ni][r] = 0.f;

        #pragma unroll
        for (int kk = 0; kk < 8; kk++) {
            const int kb = kk * 8;
            const uint32_t a0 = __float_as_uint(Qs[(rlo    ) * QS_STR + kb + fc    ]);
            const uint32_t a1 = __float_as_uint(Qs[(rlo + 8) * QS_STR + kb + fc    ]);
            const uint32_t a2 = __float_as_uint(Qs[(rlo    ) * QS_STR + kb + fc + 4]);
            const uint32_t a3 = __float_as_uint(Qs[(rlo + 8) * QS_STR + kb + fc + 4]);
            #pragma unroll
            for (int ni = 0; ni < 8; ni++) {
                const uint32_t b0 = __float_as_uint(Kb[(ni*8 + fr) * QS_STR + kb + fc    ]);
                const uint32_t b1 = __float_as_uint(Kb[(ni*8 + fr) * QS_STR + kb + fc + 4]);
                mma_tf32(accS[ni][0], accS[ni][1], accS[ni][2], accS[ni][3],
                         a0, a1, a2, a3, b0, b1);
            }
        }

        // ---- scale + mask + online softmax ----
        const bool diag = (kt == qt);
        float mx0 = -INFINITY, mx1 = -INFINITY;
        #pragma unroll
        for (int ni = 0; ni < 8; ni++) {
            float s0 = accS[ni][0] * 0.125f;
            float s1 = accS[ni][1] * 0.125f;
            float s2 = accS[ni][2] * 0.125f;
            float s3 = accS[ni][3] * 0.125f;
            if (diag) {
                const int j = ni * 8 + 2 * fc;
                if (j     > rlo    ) s0 = -INFINITY;
                if (j + 1 > rlo    ) s1 = -INFINITY;
                if (j     > rlo + 8) s2 = -INFINITY;
                if (j + 1 > rlo + 8) s3 = -INFINITY;
            }
            accS[ni][0] = s0; accS[ni][1] = s1;
            accS[ni][2] = s2; accS[ni][3] = s3;
            mx0 = fmaxf(mx0, fmaxf(s0, s1));
            mx1 = fmaxf(mx1, fmaxf(s2, s3));
        }
        mx0 = fmaxf(mx0, __shfl_xor_sync(0xffffffffu, mx0, 1));
        mx0 = fmaxf(mx0, __shfl_xor_sync(0xffffffffu, mx0, 2));
        mx1 = fmaxf(mx1, __shfl_xor_sync(0xffffffffu, mx1, 1));
        mx1 = fmaxf(mx1, __shfl_xor_sync(0xffffffffu, mx1, 2));

        const float mn0 = fmaxf(m0, mx0);
        const float mn1 = fmaxf(m1, mx1);
        const float c0 = __expf(m0 - mn0);
        const float c1 = __expf(m1 - mn1);

        float ls0 = 0.f, ls1 = 0.f;
        #pragma unroll
        for (int ni = 0; ni < 8; ni++) {
            const float p0 = __expf(accS[ni][0] - mn0);
            const float p1 = __expf(accS[ni][1] - mn0);
            const float p2 = __expf(accS[ni][2] - mn1);
            const float p3 = __expf(accS[ni][3] - mn1);
            ls0 += p0 + p1;  ls1 += p2 + p3;
            accO[ni][0] *= c0; accO[ni][1] *= c0;
            accO[ni][2] *= c1; accO[ni][3] *= c1;
            const int colp = ni * 8 + 2 * fc;
            Ps_w[(fr    ) * QS_STR + colp    ] = tf32_round(p0);
            Ps_w[(fr    ) * QS_STR + colp + 1] = tf32_round(p1);
            Ps_w[(fr + 8) * QS_STR + colp    ] = tf32_round(p2);
            Ps_w[(fr + 8) * QS_STR + colp + 1] = tf32_round(p3);
        }
        ls0 += __shfl_xor_sync(0xffffffffu, ls0, 1);
        ls0 += __shfl_xor_sync(0xffffffffu, ls0, 2);
        ls1 += __shfl_xor_sync(0xffffffffu, ls1, 1);
        ls1 += __shfl_xor_sync(0xffffffffu, ls1, 2);
        l0 = l0 * c0 + ls0;
        l1 = l1 * c1 + ls1;
        m0 = mn0; m1 = mn1;

        __syncwarp();

        // ---- O += P V ----
        #pragma unroll
        for (int kk = 0; kk < 8; kk++) {
            const int kb = kk * 8;
            const uint32_t a0 = __float_as_uint(Ps_w[(fr    ) * QS_STR + kb + fc    ]);
            const uint32_t a1 = __float_as_uint(Ps_w[(fr + 8) * QS_STR + kb + fc    ]);
            const uint32_t a2 = __float_as_uint(Ps_w[(fr    ) * QS_STR + kb + fc + 4]);
            const uint32_t a3 = __float_as_uint(Ps_w[(fr + 8) * QS_STR + kb + fc + 4]);
            #pragma unroll
            for (int ni = 0; ni < 8; ni++) {
                const uint32_t b0 = __float_as_uint(Vb[(kb + fc    ) * VS_STR + ni*8 + fr]);
                const uint32_t b1 = __float_as_uint(Vb[(kb + fc + 4) * VS_STR + ni*8 + fr]);
                mma_tf32(accO[ni][0], accO[ni][1], accO[ni][2], accO[ni][3],
                         a0, a1, a2, a3, b0, b1);
            }
        }

        __syncthreads();
        buf ^= 1;
    }

    // ---- epilogue ----
    const float inv0 = 1.f / l0;
    const float inv1 = 1.f / l1;
    const size_t grow = (size_t)(b * T_ + qt * 64 + rlo);
    #pragma unroll
    for (int ni = 0; ni < 8; ni++) {
        const int col = h * D_ + ni * 8 + 2 * fc;
        *(float2*)(y + grow * C_ + col) =
            make_float2(accO[ni][0] * inv0, accO[ni][1] * inv0);
        *(float2*)(y + (grow + 8) * C_ + col) =
            make_float2(accO[ni][2] * inv1, accO[ni][3] * inv1);
    }
}

// ---------------------------------------------------------------------------
// Launch
// ---------------------------------------------------------------------------
extern "C" void kernel_launch(void* const* d_in, const int* in_sizes, int n_in,
                              void* d_out, int out_size)
{
    (void)in_sizes; (void)n_in; (void)out_size;
    const float* x     = (const float*)d_in[0];
    const float* ln1_w = (const float*)d_in[1];
    const float* ln1_b = (const float*)d_in[2];
    const float* w_qkv = (const float*)d_in[3];
    const float* b_qkv = (const float*)d_in[4];
    const float* w_o   = (const float*)d_in[5];
    const float* b_o   = (const float*)d_in[6];
    const float* ln2_w = (const float*)d_in[7];
    const float* ln2_b = (const float*)d_in[8];
    const float* w_fc  = (const float*)d_in[9];
    const float* b_fc  = (const float*)d_in[10];
    const float* w_out = (const float*)d_in[11];
    const float* b_out = (const float*)d_in[12];
    float* out = (float*)d_out;

    float *xn, *qkv, *y, *x1, *hbuf;
    cudaGetSymbolAddress((void**)&xn,   g_xn);
    cudaGetSymbolAddress((void**)&qkv,  g_qkv);
    cudaGetSymbolAddress((void**)&y,    g_y);
    cudaGetSymbolAddress((void**)&x1,   g_x1);
    cudaGetSymbolAddress((void**)&hbuf, g_h);

    cudaFuncSetAttribute(gemm_tc_kernel<0,0,1>,
        cudaFuncAttributeMaxDynamicSharedMemorySize, SMEM_BYTES);
    cudaFuncSetAttribute(gemm_tc_kernel<0,1,0>,
        cudaFuncAttributeMaxDynamicSharedMemorySize, SMEM_BYTES);
    cudaFuncSetAttribute(gemm_tc_kernel<1,0,0>,
        cudaFuncAttributeMaxDynamicSharedMemorySize, SMEM_BYTES);
    cudaFuncSetAttribute(attn_tc_kernel,
        cudaFuncAttributeMaxDynamicSharedMemorySize, ATTN_SMEM_BYTES);

    // 1) LN1
    ln_kernel<<<M_, 256>>>(x, ln1_w, ln1_b, xn);
    // 2) qkv = xn @ w_qkv + b_qkv  (outputs tf32-rounded for attention)
    gemm_tc_kernel<0,0,1><<<dim3(3 * C_ / BN, M_ / BM), 256, SMEM_BYTES>>>(
        xn, w_qkv, b_qkv, nullptr, qkv, M_, 3 * C_, C_);
    // 3) causal attention -> y
    attn_tc_kernel<<<dim3(T_ / 64, H_, B_), 128, ATTN_SMEM_BYTES>>>(qkv, y);
    // 4) x1 = x + y @ w_o + b_o
    gemm_tc_kernel<0,1,0><<<dim3(C_ / BN, M_ / BM), 256, SMEM_BYTES>>>(
        y, w_o, b_o, x, x1, M_, C_, C_);
    // 5) LN2
    ln_kernel<<<M_, 256>>>(x1, ln2_w, ln2_b, xn);
    // 6) h = gelu(xn @ w_fc + b_fc)
    gemm_tc_kernel<1,0,0><<<dim3(FF_ / BN, M_ / BM), 256, SMEM_BYTES>>>(
        xn, w_fc, b_fc, nullptr, hbuf, M_, FF_, C_);
    // 7) out = x1 + h @ w_out + b_out
    gemm_tc_kernel<0,1,0><<<dim3(C_ / BN, M_ / BM), 256, SMEM_BYTES>>>(
        hbuf, w_out, b_out, x1, out, M_, C_, FF_);
}

// round 6
// speedup vs baseline: 4.4045x; 1.0109x over previous
#include <cuda_runtime.h>
#include <math.h>
#include <stdint.h>

// Problem constants
#define B_  4
#define T_  2048
#define H_  16
#define D_  64
#define C_  1024
#define FF_ 4096
#define M_  (B_ * T_)   // 8192 rows

// ---------------------------------------------------------------------------
// Scratch (device globals — no runtime allocation allowed)
// ---------------------------------------------------------------------------
__device__ float g_xn  [M_ * C_];
__device__ float g_qkv [M_ * 3 * C_];
__device__ float g_y   [M_ * C_];
__device__ float g_x1  [M_ * C_];
__device__ float g_h   [M_ * FF_];
// tf32-rounded weight copies
__device__ float g_wqkv[C_ * 3 * C_];
__device__ float g_wo  [C_ * C_];
__device__ float g_wfc [C_ * FF_];
__device__ float g_wout[FF_ * C_];

// ---------------------------------------------------------------------------
// Helpers
// ---------------------------------------------------------------------------
__device__ __forceinline__ uint32_t f2tf32(float f) {
    uint32_t r;
    asm("cvt.rna.tf32.f32 %0, %1;" : "=r"(r) : "f"(f));
    return r;
}
__device__ __forceinline__ float tf32_round(float f) {
    return __uint_as_float(f2tf32(f));
}

__device__ __forceinline__ void mma_tf32(
    float& d0, float& d1, float& d2, float& d3,
    uint32_t a0, uint32_t a1, uint32_t a2, uint32_t a3,
    uint32_t b0, uint32_t b1)
{
    asm volatile(
        "mma.sync.aligned.m16n8k8.row.col.f32.tf32.tf32.f32 "
        "{%0,%1,%2,%3}, {%4,%5,%6,%7}, {%8,%9}, {%0,%1,%2,%3};\n"
        : "+f"(d0), "+f"(d1), "+f"(d2), "+f"(d3)
        : "r"(a0), "r"(a1), "r"(a2), "r"(a3), "r"(b0), "r"(b1));
}

__device__ __forceinline__ void cp_async16(void* dst_smem, const void* src) {
    uint32_t d = (uint32_t)__cvta_generic_to_shared(dst_smem);
    asm volatile("cp.async.cg.shared.global [%0], [%1], 16;\n" :: "r"(d), "l"(src));
}
__device__ __forceinline__ void cp_commit() {
    asm volatile("cp.async.commit_group;\n");
}
template<int N>
__device__ __forceinline__ void cp_wait() {
    asm volatile("cp.async.wait_group %0;\n" :: "n"(N));
}

__device__ __forceinline__ float gelu_exact(float x) {
    return 0.5f * x * (1.0f + erff(x * 0.70710678118654752f));
}

// ---------------------------------------------------------------------------
// Elementwise tf32 rounding (for weights), float4 vectorized
// ---------------------------------------------------------------------------
__global__ void __launch_bounds__(256) round_kernel(
    const float* __restrict__ src, float* __restrict__ dst, int n4)
{
    const int i = blockIdx.x * 256 + threadIdx.x;
    if (i < n4) {
        float4 v = ((const float4*)src)[i];
        v.x = tf32_round(v.x); v.y = tf32_round(v.y);
        v.z = tf32_round(v.z); v.w = tf32_round(v.w);
        ((float4*)dst)[i] = v;
    }
}

// ---------------------------------------------------------------------------
// LayerNorm (outputs tf32-rounded — they feed GEMM A-sides)
// ---------------------------------------------------------------------------
__global__ void __launch_bounds__(256) ln_kernel(
    const float* __restrict__ x, const float* __restrict__ w,
    const float* __restrict__ b, float* __restrict__ out)
{
    const int row = blockIdx.x;
    const int tid = threadIdx.x;
    const float4 v = ((const float4*)(x + (size_t)row * C_))[tid];

    float s  = v.x + v.y + v.z + v.w;
    float s2 = v.x*v.x + v.y*v.y + v.z*v.z + v.w*v.w;

    #pragma unroll
    for (int o = 16; o > 0; o >>= 1) {
        s  += __shfl_xor_sync(0xffffffffu, s,  o);
        s2 += __shfl_xor_sync(0xffffffffu, s2, o);
    }

    __shared__ float red[18];
    const int warp = tid >> 5, lane = tid & 31;
    if (lane == 0) { red[warp] = s; red[8 + warp] = s2; }
    __syncthreads();
    if (warp == 0) {
        float a  = (lane < 8) ? red[lane]     : 0.f;
        float a2 = (lane < 8) ? red[8 + lane] : 0.f;
        #pragma unroll
        for (int o = 4; o > 0; o >>= 1) {
            a  += __shfl_xor_sync(0xffffffffu, a,  o);
            a2 += __shfl_xor_sync(0xffffffffu, a2, o);
        }
        if (lane == 0) { red[16] = a * (1.0f / C_); red[17] = a2 * (1.0f / C_); }
    }
    __syncthreads();

    const float mean = red[16];
    const float var  = red[17] - mean * mean;
    const float rstd = rsqrtf(var + 1e-5f);

    const float4 wv = ((const float4*)w)[tid];
    const float4 bv = ((const float4*)b)[tid];
    float4 o4;
    o4.x = tf32_round((v.x - mean) * rstd * wv.x + bv.x);
    o4.y = tf32_round((v.y - mean) * rstd * wv.y + bv.y);
    o4.z = tf32_round((v.z - mean) * rstd * wv.z + bv.z);
    o4.w = tf32_round((v.w - mean) * rstd * wv.w + bv.w);
    ((float4*)(out + (size_t)row * C_))[tid] = o4;
}

// ---------------------------------------------------------------------------
// TF32 tensor-core GEMM. CTA tile 128x256x32, 8 warps (2x4) of 64x64.
// 3-stage cp.async pipeline. Inputs MUST already be tf32-rounded (no cvt in
// the inner loop). fp32 accumulation.
// ---------------------------------------------------------------------------
#define BM 128
#define BN 256
#define BK 32
#define STAGES 3
#define A_STRIDE 36    // 36 % 32 == 4  -> conflict-free A fragment loads
#define B_STRIDE 264   // 264 % 32 == 8 -> conflict-free B fragment loads
#define A_TILE_FLOATS (BM * A_STRIDE)   // 4608
#define B_TILE_FLOATS (BK * B_STRIDE)   // 8448
#define SMEM_BYTES (STAGES * (A_TILE_FLOATS + B_TILE_FLOATS) * 4)  // 156672

template<int ACT, int RES, int CVT>
__global__ void __launch_bounds__(256) gemm_tc_kernel(
    const float* __restrict__ A, const float* __restrict__ W,
    const float* __restrict__ bias, const float* __restrict__ res,
    float* __restrict__ out, int M, int N, int K)
{
    extern __shared__ float smem[];
    float* As = smem;
    float* Bs = smem + STAGES * A_TILE_FLOATS;

    const int tid  = threadIdx.x;
    const int lane = tid & 31;
    const int wid  = tid >> 5;
    const int wm   = wid >> 2;                // 0..1 : 64-row band
    const int wn   = wid & 3;                 // 0..3 : 64-col band
    const int bm   = blockIdx.y;
    const int bn   = blockIdx.x;
    const int fr   = lane >> 2;               // 0..7
    const int fc   = lane & 3;                // 0..3

    float acc[4][8][4];
    #pragma unroll
    for (int i = 0; i < 4; i++)
        #pragma unroll
        for (int j = 0; j < 8; j++)
            #pragma unroll
            for (int r = 0; r < 4; r++) acc[i][j][r] = 0.f;

    const int ntiles = K / BK;

    auto load_tile = [&](int t, int stg) {
        const int k0 = t * BK;
        float* Ab = As + stg * A_TILE_FLOATS;
        float* Bb = Bs + stg * B_TILE_FLOATS;
        #pragma unroll
        for (int i = 0; i < 4; i++) {         // A: 128 rows x 8 float4
            const int idx = i * 256 + tid;
            const int row = idx >> 3, c4 = idx & 7;
            cp_async16(Ab + row * A_STRIDE + c4 * 4,
                       A + (size_t)(bm * BM + row) * K + k0 + c4 * 4);
        }
        #pragma unroll
        for (int i = 0; i < 8; i++) {         // B: 32 rows x 64 float4
            const int idx = i * 256 + tid;
            const int row = idx >> 6, c4 = idx & 63;
            cp_async16(Bb + row * B_STRIDE + c4 * 4,
                       W + (size_t)(k0 + row) * N + bn * BN + c4 * 4);
        }
        cp_commit();
    };

    load_tile(0, 0);
    load_tile(1, 1);

    for (int t = 0; t < ntiles; t++) {
        if (t + 2 < ntiles) load_tile(t + 2, (t + 2) % STAGES);
        else                cp_commit();      // empty group keeps accounting uniform
        cp_wait<2>();                         // tile t's group complete
        __syncthreads();

        const float* Ab = As + (t % STAGES) * A_TILE_FLOATS;
        const float* Bb = Bs + (t % STAGES) * B_TILE_FLOATS;

        #pragma unroll
        for (int kk = 0; kk < 4; kk++) {
            const int kb = kk * 8;
            uint32_t af[4][4], bf[8][2];
            #pragma unroll
            for (int mi = 0; mi < 4; mi++) {
                const int rb = wm * 64 + mi * 16;
                af[mi][0] = __float_as_uint(Ab[(rb + fr    ) * A_STRIDE + kb + fc    ]);
                af[mi][1] = __float_as_uint(Ab[(rb + fr + 8) * A_STRIDE + kb + fc    ]);
                af[mi][2] = __float_as_uint(Ab[(rb + fr    ) * A_STRIDE + kb + fc + 4]);
                af[mi][3] = __float_as_uint(Ab[(rb + fr + 8) * A_STRIDE + kb + fc + 4]);
            }
            #pragma unroll
            for (int ni = 0; ni < 8; ni++) {
                const int cb = wn * 64 + ni * 8 + fr;
                bf[ni][0] = __float_as_uint(Bb[(kb + fc    ) * B_STRIDE + cb]);
                bf[ni][1] = __float_as_uint(Bb[(kb + fc + 4) * B_STRIDE + cb]);
            }
            #pragma unroll
            for (int mi = 0; mi < 4; mi++)
                #pragma unroll
                for (int ni = 0; ni < 8; ni++)
                    mma_tf32(acc[mi][ni][0], acc[mi][ni][1],
                             acc[mi][ni][2], acc[mi][ni][3],
                             af[mi][0], af[mi][1], af[mi][2], af[mi][3],
                             bf[ni][0], bf[ni][1]);
        }
        __syncthreads();
    }

    // ---- epilogue ----
    #pragma unroll
    for (int mi = 0; mi < 4; mi++) {
        const int row0 = bm * BM + wm * 64 + mi * 16 + fr;
        #pragma unroll
        for (int ni = 0; ni < 8; ni++) {
            const int col = bn * BN + wn * 64 + ni * 8 + fc * 2;
            const float b0 = bias[col], b1 = bias[col + 1];

            float v0 = acc[mi][ni][0] + b0;
            float v1 = acc[mi][ni][1] + b1;
            float v2 = acc[mi][ni][2] + b0;
            float v3 = acc[mi][ni][3] + b1;
            if (ACT == 1) {
                v0 = gelu_exact(v0); v1 = gelu_exact(v1);
                v2 = gelu_exact(v2); v3 = gelu_exact(v3);
            }
            if (RES) {
                const float2 r0 = *(const float2*)(res + (size_t)row0 * N + col);
                const float2 r1 = *(const float2*)(res + (size_t)(row0 + 8) * N + col);
                v0 += r0.x; v1 += r0.y; v2 += r1.x; v3 += r1.y;
            }
            if (CVT) {
                v0 = tf32_round(v0); v1 = tf32_round(v1);
                v2 = tf32_round(v2); v3 = tf32_round(v3);
            }
            *(float2*)(out + (size_t)row0 * N + col)       = make_float2(v0, v1);
            *(float2*)(out + (size_t)(row0 + 8) * N + col) = make_float2(v2, v3);
        }
    }
}

// ---------------------------------------------------------------------------
// Tensor-core causal flash attention (tf32). Unchanged from R5 except the
// output is tf32-rounded (it feeds the proj GEMM A-side).
// ---------------------------------------------------------------------------
#define QS_STR 68
#define VS_STR 72
#define QS_FLOATS (64 * QS_STR)
#define KS_FLOATS (64 * QS_STR)
#define VS_FLOATS (64 * VS_STR)
#define PS_FLOATS (64 * QS_STR)
#define ATTN_SMEM_BYTES ((QS_FLOATS + 2*KS_FLOATS + 2*VS_FLOATS + PS_FLOATS) * 4)

__global__ void __launch_bounds__(128) attn_tc_kernel(
    const float* __restrict__ qkv, float* __restrict__ y)
{
    extern __shared__ float sm[];
    float* Qs = sm;
    float* Ks = Qs + QS_FLOATS;
    float* Vs = Ks + 2 * KS_FLOATS;
    float* Ps = Vs + 2 * VS_FLOATS;

    const int qt   = blockIdx.x;
    const int h    = blockIdx.y;
    const int b    = blockIdx.z;
    const int tid  = threadIdx.x;
    const int lane = tid & 31;
    const int w    = tid >> 5;
    const int fr   = lane >> 2;
    const int fc   = lane & 3;

    const size_t base = (size_t)(b * T_) * (3 * C_) + h * D_;

    {
        #pragma unroll
        for (int i = 0; i < 8; i++) {
            const int idx = i * 128 + tid;
            const int r = idx >> 4, c4 = idx & 15;
            const float* src = qkv + base + (size_t)(qt * 64 + r) * (3 * C_) + c4 * 4;
            cp_async16(Qs + r * QS_STR + c4 * 4, src);
        }
        #pragma unroll
        for (int i = 0; i < 8; i++) {
            const int idx = i * 128 + tid;
            const int r = idx >> 4, c4 = idx & 15;
            const float* src = qkv + base + (size_t)(r) * (3 * C_) + c4 * 4;
            cp_async16(Ks + r * QS_STR + c4 * 4, src + C_);
            cp_async16(Vs + r * VS_STR + c4 * 4, src + 2 * C_);
        }
        cp_commit();
    }

    auto load_kv = [&](int kt, int bufi) {
        float* Kb = Ks + bufi * KS_FLOATS;
        float* Vb = Vs + bufi * VS_FLOATS;
        #pragma unroll
        for (int i = 0; i < 8; i++) {
            const int idx = i * 128 + tid;
            const int r = idx >> 4, c4 = idx & 15;
            const float* src = qkv + base + (size_t)(kt * 64 + r) * (3 * C_) + c4 * 4;
            cp_async16(Kb + r * QS_STR + c4 * 4, src + C_);
            cp_async16(Vb + r * VS_STR + c4 * 4, src + 2 * C_);
        }
        cp_commit();
    };

    float accO[8][4];
    #pragma unroll
    for (int ni = 0; ni < 8; ni++)
        #pragma unroll
        for (int r = 0; r < 4; r++) accO[ni][r] = 0.f;
    float m0 = -INFINITY, m1 = -INFINITY, l0 = 0.f, l1 = 0.f;

    float* Ps_w = Ps + w * 16 * QS_STR;
    const int rlo = w * 16 + fr;

    int buf = 0;
    for (int kt = 0; kt <= qt; kt++) {
        if (kt < qt) { load_kv(kt + 1, buf ^ 1); cp_wait<1>(); }
        else         { cp_wait<0>(); }
        __syncthreads();

        const float* Kb = Ks + buf * KS_FLOATS;
        const float* Vb = Vs + buf * VS_FLOATS;

        float accS[8][4];
        #pragma unroll
        for (int ni = 0; ni < 8; ni++)
            #pragma unroll
            for (int r = 0; r < 4; r++) accS[ni][r] = 0.f;

        #pragma unroll
        for (int kk = 0; kk < 8; kk++) {
            const int kb = kk * 8;
            const uint32_t a0 = __float_as_uint(Qs[(rlo    ) * QS_STR + kb + fc    ]);
            const uint32_t a1 = __float_as_uint(Qs[(rlo + 8) * QS_STR + kb + fc    ]);
            const uint32_t a2 = __float_as_uint(Qs[(rlo    ) * QS_STR + kb + fc + 4]);
            const uint32_t a3 = __float_as_uint(Qs[(rlo + 8) * QS_STR + kb + fc + 4]);
            #pragma unroll
            for (int ni = 0; ni < 8; ni++) {
                const uint32_t b0 = __float_as_uint(Kb[(ni*8 + fr) * QS_STR + kb + fc    ]);
                const uint32_t b1 = __float_as_uint(Kb[(ni*8 + fr) * QS_STR + kb + fc + 4]);
                mma_tf32(accS[ni][0], accS[ni][1], accS[ni][2], accS[ni][3],
                         a0, a1, a2, a3, b0, b1);
            }
        }

        const bool diag = (kt == qt);
        float mx0 = -INFINITY, mx1 = -INFINITY;
        #pragma unroll
        for (int ni = 0; ni < 8; ni++) {
            float s0 = accS[ni][0] * 0.125f;
            float s1 = accS[ni][1] * 0.125f;
            float s2 = accS[ni][2] * 0.125f;
            float s3 = accS[ni][3] * 0.125f;
            if (diag) {
                const int j = ni * 8 + 2 * fc;
                if (j     > rlo    ) s0 = -INFINITY;
                if (j + 1 > rlo    ) s1 = -INFINITY;
                if (j     > rlo + 8) s2 = -INFINITY;
                if (j + 1 > rlo + 8) s3 = -INFINITY;
            }
            accS[ni][0] = s0; accS[ni][1] = s1;
            accS[ni][2] = s2; accS[ni][3] = s3;
            mx0 = fmaxf(mx0, fmaxf(s0, s1));
            mx1 = fmaxf(mx1, fmaxf(s2, s3));
        }
        mx0 = fmaxf(mx0, __shfl_xor_sync(0xffffffffu, mx0, 1));
        mx0 = fmaxf(mx0, __shfl_xor_sync(0xffffffffu, mx0, 2));
        mx1 = fmaxf(mx1, __shfl_xor_sync(0xffffffffu, mx1, 1));
        mx1 = fmaxf(mx1, __shfl_xor_sync(0xffffffffu, mx1, 2));

        const float mn0 = fmaxf(m0, mx0);
        const float mn1 = fmaxf(m1, mx1);
        const float c0 = __expf(m0 - mn0);
        const float c1 = __expf(m1 - mn1);

        float ls0 = 0.f, ls1 = 0.f;
        #pragma unroll
        for (int ni = 0; ni < 8; ni++) {
            const float p0 = __expf(accS[ni][0] - mn0);
            const float p1 = __expf(accS[ni][1] - mn0);
            const float p2 = __expf(accS[ni][2] - mn1);
            const float p3 = __expf(accS[ni][3] - mn1);
            ls0 += p0 + p1;  ls1 += p2 + p3;
            accO[ni][0] *= c0; accO[ni][1] *= c0;
            accO[ni][2] *= c1; accO[ni][3] *= c1;
            const int colp = ni * 8 + 2 * fc;
            Ps_w[(fr    ) * QS_STR + colp    ] = tf32_round(p0);
            Ps_w[(fr    ) * QS_STR + colp + 1] = tf32_round(p1);
            Ps_w[(fr + 8) * QS_STR + colp    ] = tf32_round(p2);
            Ps_w[(fr + 8) * QS_STR + colp + 1] = tf32_round(p3);
        }
        ls0 += __shfl_xor_sync(0xffffffffu, ls0, 1);
        ls0 += __shfl_xor_sync(0xffffffffu, ls0, 2);
        ls1 += __shfl_xor_sync(0xffffffffu, ls1, 1);
        ls1 += __shfl_xor_sync(0xffffffffu, ls1, 2);
        l0 = l0 * c0 + ls0;
        l1 = l1 * c1 + ls1;
        m0 = mn0; m1 = mn1;

        __syncwarp();

        #pragma unroll
        for (int kk = 0; kk < 8; kk++) {
            const int kb = kk * 8;
            const uint32_t a0 = __float_as_uint(Ps_w[(fr    ) * QS_STR + kb + fc    ]);
            const uint32_t a1 = __float_as_uint(Ps_w[(fr + 8) * QS_STR + kb + fc    ]);
            const uint32_t a2 = __float_as_uint(Ps_w[(fr    ) * QS_STR + kb + fc + 4]);
            const uint32_t a3 = __float_as_uint(Ps_w[(fr + 8) * QS_STR + kb + fc + 4]);
            #pragma unroll
            for (int ni = 0; ni < 8; ni++) {
                const uint32_t b0 = __float_as_uint(Vb[(kb + fc    ) * VS_STR + ni*8 + fr]);
                const uint32_t b1 = __float_as_uint(Vb[(kb + fc + 4) * VS_STR + ni*8 + fr]);
                mma_tf32(accO[ni][0], accO[ni][1], accO[ni][2], accO[ni][3],
                         a0, a1, a2, a3, b0, b1);
            }
        }

        __syncthreads();
        buf ^= 1;
    }

    const float inv0 = 1.f / l0;
    const float inv1 = 1.f / l1;
    const size_t grow = (size_t)(b * T_ + qt * 64 + rlo);
    #pragma unroll
    for (int ni = 0; ni < 8; ni++) {
        const int col = h * D_ + ni * 8 + 2 * fc;
        *(float2*)(y + grow * C_ + col) =
            make_float2(tf32_round(accO[ni][0] * inv0), tf32_round(accO[ni][1] * inv0));
        *(float2*)(y + (grow + 8) * C_ + col) =
            make_float2(tf32_round(accO[ni][2] * inv1), tf32_round(accO[ni][3] * inv1));
    }
}

// ---------------------------------------------------------------------------
// Launch
// ---------------------------------------------------------------------------
extern "C" void kernel_launch(void* const* d_in, const int* in_sizes, int n_in,
                              void* d_out, int out_size)
{
    (void)in_sizes; (void)n_in; (void)out_size;
    const float* x     = (const float*)d_in[0];
    const float* ln1_w = (const float*)d_in[1];
    const float* ln1_b = (const float*)d_in[2];
    const float* w_qkv = (const float*)d_in[3];
    const float* b_qkv = (const float*)d_in[4];
    const float* w_o   = (const float*)d_in[5];
    const float* b_o   = (const float*)d_in[6];
    const float* ln2_w = (const float*)d_in[7];
    const float* ln2_b = (const float*)d_in[8];
    const float* w_fc  = (const float*)d_in[9];
    const float* b_fc  = (const float*)d_in[10];
    const float* w_out = (const float*)d_in[11];
    const float* b_out = (const float*)d_in[12];
    float* out = (float*)d_out;

    float *xn, *qkv, *y, *x1, *hbuf, *wq, *wo, *wf, *wu;
    cudaGetSymbolAddress((void**)&xn,   g_xn);
    cudaGetSymbolAddress((void**)&qkv,  g_qkv);
    cudaGetSymbolAddress((void**)&y,    g_y);
    cudaGetSymbolAddress((void**)&x1,   g_x1);
    cudaGetSymbolAddress((void**)&hbuf, g_h);
    cudaGetSymbolAddress((void**)&wq,   g_wqkv);
    cudaGetSymbolAddress((void**)&wo,   g_wo);
    cudaGetSymbolAddress((void**)&wf,   g_wfc);
    cudaGetSymbolAddress((void**)&wu,   g_wout);

    cudaFuncSetAttribute(gemm_tc_kernel<0,0,1>,
        cudaFuncAttributeMaxDynamicSharedMemorySize, SMEM_BYTES);
    cudaFuncSetAttribute(gemm_tc_kernel<0,1,0>,
        cudaFuncAttributeMaxDynamicSharedMemorySize, SMEM_BYTES);
    cudaFuncSetAttribute(gemm_tc_kernel<1,0,1>,
        cudaFuncAttributeMaxDynamicSharedMemorySize, SMEM_BYTES);
    cudaFuncSetAttribute(attn_tc_kernel,
        cudaFuncAttributeMaxDynamicSharedMemorySize, ATTN_SMEM_BYTES);

    // 0) one-time (per replay) tf32 rounding of weights
    round_kernel<<<(C_*3*C_/4 + 255)/256, 256>>>(w_qkv, wq, C_*3*C_/4);
    round_kernel<<<(C_*C_/4   + 255)/256, 256>>>(w_o,   wo, C_*C_/4);
    round_kernel<<<(C_*FF_/4  + 255)/256, 256>>>(w_fc,  wf, C_*FF_/4);
    round_kernel<<<(FF_*C_/4  + 255)/256, 256>>>(w_out, wu, FF_*C_/4);

    // 1) LN1 (tf32-rounded output)
    ln_kernel<<<M_, 256>>>(x, ln1_w, ln1_b, xn);
    // 2) qkv = xn @ w_qkv + b_qkv (tf32-rounded output for attention)
    gemm_tc_kernel<0,0,1><<<dim3(3 * C_ / BN, M_ / BM), 256, SMEM_BYTES>>>(
        xn, wq, b_qkv, nullptr, qkv, M_, 3 * C_, C_);
    // 3) causal attention -> y (tf32-rounded)
    attn_tc_kernel<<<dim3(T_ / 64, H_, B_), 128, ATTN_SMEM_BYTES>>>(qkv, y);
    // 4) x1 = x + y @ w_o + b_o (full fp32 residual)
    gemm_tc_kernel<0,1,0><<<dim3(C_ / BN, M_ / BM), 256, SMEM_BYTES>>>(
        y, wo, b_o, x, x1, M_, C_, C_);
    // 5) LN2 (tf32-rounded output)
    ln_kernel<<<M_, 256>>>(x1, ln2_w, ln2_b, xn);
    // 6) h = gelu(xn @ w_fc + b_fc) (tf32-rounded output)
    gemm_tc_kernel<1,0,1><<<dim3(FF_ / BN, M_ / BM), 256, SMEM_BYTES>>>(
        xn, wf, b_fc, nullptr, hbuf, M_, FF_, C_);
    // 7) out = x1 + h @ w_out + b_out (full fp32)
    gemm_tc_kernel<0,1,0><<<dim3(C_ / BN, M_ / BM), 256, SMEM_BYTES>>>(
        hbuf, wu, b_out, x1, out, M_, C_, FF_);
}

// round 7
// speedup vs baseline: 6.6223x; 1.5036x over previous
#include <cuda_runtime.h>
#include <cuda_fp16.h>
#include <math.h>
#include <stdint.h>

// Problem constants
#define B_  4
#define T_  2048
#define H_  16
#define D_  64
#define C_  1024
#define FF_ 4096
#define M_  (B_ * T_)   // 8192 rows

// ---------------------------------------------------------------------------
// Scratch (device globals — no runtime allocation allowed)
// ---------------------------------------------------------------------------
__device__ __half g_xn  [M_ * C_];        // LN output (fp16, GEMM A-side)
__device__ float  g_qkv [M_ * 3 * C_];    // qkv (fp32, tf32-rounded, for attn)
__device__ __half g_y   [M_ * C_];        // attention output (fp16)
__device__ float  g_x1  [M_ * C_];        // first residual (fp32)
__device__ __half g_h   [M_ * FF_];       // gelu(fc) activations (fp16)
// fp16 k-pair-interleaved weights: element (k,n) at  (k>>1)*2N + 2n + (k&1)
__device__ __half g_wqkv[C_ * 3 * C_];
__device__ __half g_wo  [C_ * C_];
__device__ __half g_wfc [C_ * FF_];
__device__ __half g_wout[FF_ * C_];

// ---------------------------------------------------------------------------
// Helpers
// ---------------------------------------------------------------------------
__device__ __forceinline__ uint32_t f2tf32(float f) {
    uint32_t r;
    asm("cvt.rna.tf32.f32 %0, %1;" : "=r"(r) : "f"(f));
    return r;
}
__device__ __forceinline__ float tf32_round(float f) {
    return __uint_as_float(f2tf32(f));
}

__device__ __forceinline__ void mma_tf32(
    float& d0, float& d1, float& d2, float& d3,
    uint32_t a0, uint32_t a1, uint32_t a2, uint32_t a3,
    uint32_t b0, uint32_t b1)
{
    asm volatile(
        "mma.sync.aligned.m16n8k8.row.col.f32.tf32.tf32.f32 "
        "{%0,%1,%2,%3}, {%4,%5,%6,%7}, {%8,%9}, {%0,%1,%2,%3};\n"
        : "+f"(d0), "+f"(d1), "+f"(d2), "+f"(d3)
        : "r"(a0), "r"(a1), "r"(a2), "r"(a3), "r"(b0), "r"(b1));
}

__device__ __forceinline__ void mma_f16(
    float& d0, float& d1, float& d2, float& d3,
    uint32_t a0, uint32_t a1, uint32_t a2, uint32_t a3,
    uint32_t b0, uint32_t b1)
{
    asm volatile(
        "mma.sync.aligned.m16n8k16.row.col.f32.f16.f16.f32 "
        "{%0,%1,%2,%3}, {%4,%5,%6,%7}, {%8,%9}, {%0,%1,%2,%3};\n"
        : "+f"(d0), "+f"(d1), "+f"(d2), "+f"(d3)
        : "r"(a0), "r"(a1), "r"(a2), "r"(a3), "r"(b0), "r"(b1));
}

__device__ __forceinline__ void cp_async16(void* dst_smem, const void* src) {
    uint32_t d = (uint32_t)__cvta_generic_to_shared(dst_smem);
    asm volatile("cp.async.cg.shared.global [%0], [%1], 16;\n" :: "r"(d), "l"(src));
}
__device__ __forceinline__ void cp_commit() {
    asm volatile("cp.async.commit_group;\n");
}
template<int N>
__device__ __forceinline__ void cp_wait() {
    asm volatile("cp.async.wait_group %0;\n" :: "n"(N));
}

__device__ __forceinline__ float gelu_exact(float x) {
    return 0.5f * x * (1.0f + erff(x * 0.70710678118654752f));
}

// ---------------------------------------------------------------------------
// Weight prep: fp32 [K][N] -> fp16 k-pair-interleaved [K/2][N][2]
// One thread handles a (2k-row x 4col) group = 16B output.
// ---------------------------------------------------------------------------
__global__ void __launch_bounds__(256) wprep_kernel(
    const float* __restrict__ src, __half* __restrict__ dst, int K, int N)
{
    const int total = (K >> 1) * (N >> 2);
    const int idx = blockIdx.x * 256 + threadIdx.x;
    if (idx >= total) return;
    const int nq = N >> 2;
    const int kp = idx / nq;
    const int n4 = idx - kp * nq;
    const float4 r0 = *(const float4*)(src + (size_t)(2 * kp)     * N + 4 * n4);
    const float4 r1 = *(const float4*)(src + (size_t)(2 * kp + 1) * N + 4 * n4);
    __half2* d = (__half2*)(dst + (size_t)kp * (2 * N) + 8 * n4);
    d[0] = __halves2half2(__float2half_rn(r0.x), __float2half_rn(r1.x));
    d[1] = __halves2half2(__float2half_rn(r0.y), __float2half_rn(r1.y));
    d[2] = __halves2half2(__float2half_rn(r0.z), __float2half_rn(r1.z));
    d[3] = __halves2half2(__float2half_rn(r0.w), __float2half_rn(r1.w));
}

// ---------------------------------------------------------------------------
// LayerNorm: outputs fp16 (feeds GEMM A-sides)
// ---------------------------------------------------------------------------
__global__ void __launch_bounds__(256) ln_kernel(
    const float* __restrict__ x, const float* __restrict__ w,
    const float* __restrict__ b, __half* __restrict__ out)
{
    const int row = blockIdx.x;
    const int tid = threadIdx.x;
    const float4 v = ((const float4*)(x + (size_t)row * C_))[tid];

    float s  = v.x + v.y + v.z + v.w;
    float s2 = v.x*v.x + v.y*v.y + v.z*v.z + v.w*v.w;

    #pragma unroll
    for (int o = 16; o > 0; o >>= 1) {
        s  += __shfl_xor_sync(0xffffffffu, s,  o);
        s2 += __shfl_xor_sync(0xffffffffu, s2, o);
    }

    __shared__ float red[18];
    const int warp = tid >> 5, lane = tid & 31;
    if (lane == 0) { red[warp] = s; red[8 + warp] = s2; }
    __syncthreads();
    if (warp == 0) {
        float a  = (lane < 8) ? red[lane]     : 0.f;
        float a2 = (lane < 8) ? red[8 + lane] : 0.f;
        #pragma unroll
        for (int o = 4; o > 0; o >>= 1) {
            a  += __shfl_xor_sync(0xffffffffu, a,  o);
            a2 += __shfl_xor_sync(0xffffffffu, a2, o);
        }
        if (lane == 0) { red[16] = a * (1.0f / C_); red[17] = a2 * (1.0f / C_); }
    }
    __syncthreads();

    const float mean = red[16];
    const float var  = red[17] - mean * mean;
    const float rstd = rsqrtf(var + 1e-5f);

    const float4 wv = ((const float4*)w)[tid];
    const float4 bv = ((const float4*)b)[tid];
    __half2* op = (__half2*)(out + (size_t)row * C_ + 4 * tid);
    op[0] = __halves2half2(__float2half_rn((v.x - mean) * rstd * wv.x + bv.x),
                           __float2half_rn((v.y - mean) * rstd * wv.y + bv.y));
    op[1] = __halves2half2(__float2half_rn((v.z - mean) * rstd * wv.z + bv.z),
                           __float2half_rn((v.w - mean) * rstd * wv.w + bv.w));
}

// ---------------------------------------------------------------------------
// FP16 tensor-core GEMM: out[M,N] = A[M,K](f16) @ W[K,N](f16 interleaved)
//                                   + bias(f32)  (+GELU / +residual f32)
// CTA 128x128x32, 8 warps (2x4) of 64x32, mma.m16n8k16, 3-stage cp.async.
// OUT: 0 = f32, 1 = f32 tf32-rounded, 2 = f16.
// ---------------------------------------------------------------------------
#define BM 128
#define BN 128
#define BK 32
#define STAGES 3
#define A_STR 40                       // halves; bank = (20*fr+fc)%32 distinct
#define B_STR 272                      // halves per kp row; bank 8*fc+fr distinct
#define A_TILE_H (BM * A_STR)          // 5120 halves
#define B_TILE_H (16 * B_STR)          // 4352 halves
#define SMEM_BYTES (STAGES * (A_TILE_H + B_TILE_H) * 2)   // 56832

template<int ACT, int RES, int OUT>
__global__ void __launch_bounds__(256) gemm_h_kernel(
    const __half* __restrict__ A, const __half* __restrict__ Wp,
    const float* __restrict__ bias, const float* __restrict__ res,
    void* __restrict__ outv, int M, int N, int K)
{
    extern __shared__ __half hsm[];
    __half* As = hsm;
    __half* Bs = hsm + STAGES * A_TILE_H;

    const int tid  = threadIdx.x;
    const int lane = tid & 31;
    const int wid  = tid >> 5;
    const int wm   = wid >> 2;
    const int wn   = wid & 3;
    const int bm   = blockIdx.y;
    const int bn   = blockIdx.x;
    const int fr   = lane >> 2;        // 0..7
    const int fc   = lane & 3;         // 0..3

    float acc[4][4][4];
    #pragma unroll
    for (int i = 0; i < 4; i++)
        #pragma unroll
        for (int j = 0; j < 4; j++)
            #pragma unroll
            for (int r = 0; r < 4; r++) acc[i][j][r] = 0.f;

    const int ntiles = K / BK;

    auto load_tile = [&](int t, int stg) {
        const int k0 = t * BK;
        __half* Ab = As + stg * A_TILE_H;
        __half* Bb = Bs + stg * B_TILE_H;
        // A: 128 rows x 32 halves = 512 x 16B chunks
        #pragma unroll
        for (int i = 0; i < 2; i++) {
            const int idx = i * 256 + tid;
            const int row = idx >> 2, c4 = idx & 3;
            cp_async16(Ab + row * A_STR + c4 * 8,
                       A + (size_t)(bm * BM + row) * K + k0 + c4 * 8);
        }
        // B: 16 kp-rows x 256 halves = 512 x 16B chunks
        const int kp0 = k0 >> 1;
        #pragma unroll
        for (int i = 0; i < 2; i++) {
            const int idx = i * 256 + tid;
            const int kp = idx >> 5, ch = idx & 31;
            cp_async16(Bb + kp * B_STR + ch * 8,
                       Wp + (size_t)(kp0 + kp) * (2 * N) + (size_t)bn * (2 * BN) + ch * 8);
        }
        cp_commit();
    };

    load_tile(0, 0);
    load_tile(1, 1);

    for (int t = 0; t < ntiles; t++) {
        if (t + 2 < ntiles) load_tile(t + 2, (t + 2) % STAGES);
        else                cp_commit();
        cp_wait<2>();
        __syncthreads();

        const __half* Ab = As + (t % STAGES) * A_TILE_H;
        const __half* Bb = Bs + (t % STAGES) * B_TILE_H;

        #pragma unroll
        for (int ks = 0; ks < 2; ks++) {
            const int kc = ks * 16;
            uint32_t af[4][4], bf[4][2];
            #pragma unroll
            for (int mi = 0; mi < 4; mi++) {
                const int base = (wm * 64 + mi * 16 + fr) * A_STR + kc + 2 * fc;
                af[mi][0] = *(const uint32_t*)&Ab[base];
                af[mi][1] = *(const uint32_t*)&Ab[base + 8 * A_STR];
                af[mi][2] = *(const uint32_t*)&Ab[base + 8];
                af[mi][3] = *(const uint32_t*)&Ab[base + 8 * A_STR + 8];
            }
            const int kp = ks * 8 + fc;
            #pragma unroll
            for (int ni = 0; ni < 4; ni++) {
                const int n2 = 2 * (wn * 32 + ni * 8 + fr);
                bf[ni][0] = *(const uint32_t*)&Bb[kp * B_STR + n2];
                bf[ni][1] = *(const uint32_t*)&Bb[(kp + 4) * B_STR + n2];
            }
            #pragma unroll
            for (int mi = 0; mi < 4; mi++)
                #pragma unroll
                for (int ni = 0; ni < 4; ni++)
                    mma_f16(acc[mi][ni][0], acc[mi][ni][1],
                            acc[mi][ni][2], acc[mi][ni][3],
                            af[mi][0], af[mi][1], af[mi][2], af[mi][3],
                            bf[ni][0], bf[ni][1]);
        }
        __syncthreads();
    }

    // ---- epilogue ----
    #pragma unroll
    for (int mi = 0; mi < 4; mi++) {
        const int row0 = bm * BM + wm * 64 + mi * 16 + fr;
        #pragma unroll
        for (int ni = 0; ni < 4; ni++) {
            const int col = bn * BN + wn * 32 + ni * 8 + fc * 2;
            const float b0 = bias[col], b1 = bias[col + 1];

            float v0 = acc[mi][ni][0] + b0;
            float v1 = acc[mi][ni][1] + b1;
            float v2 = acc[mi][ni][2] + b0;
            float v3 = acc[mi][ni][3] + b1;
            if (ACT == 1) {
                v0 = gelu_exact(v0); v1 = gelu_exact(v1);
                v2 = gelu_exact(v2); v3 = gelu_exact(v3);
            }
            if (RES) {
                const float2 r0 = *(const float2*)(res + (size_t)row0 * N + col);
                const float2 r1 = *(const float2*)(res + (size_t)(row0 + 8) * N + col);
                v0 += r0.x; v1 += r0.y; v2 += r1.x; v3 += r1.y;
            }
            if (OUT == 2) {
                __half* out = (__half*)outv;
                *(__half2*)(out + (size_t)row0 * N + col) =
                    __halves2half2(__float2half_rn(v0), __float2half_rn(v1));
                *(__half2*)(out + (size_t)(row0 + 8) * N + col) =
                    __halves2half2(__float2half_rn(v2), __float2half_rn(v3));
            } else {
                if (OUT == 1) {
                    v0 = tf32_round(v0); v1 = tf32_round(v1);
                    v2 = tf32_round(v2); v3 = tf32_round(v3);
                }
                float* out = (float*)outv;
                *(float2*)(out + (size_t)row0 * N + col)       = make_float2(v0, v1);
                *(float2*)(out + (size_t)(row0 + 8) * N + col) = make_float2(v2, v3);
            }
        }
    }
}

// ---------------------------------------------------------------------------
// Tensor-core causal flash attention (tf32, unchanged) — output now fp16.
// ---------------------------------------------------------------------------
#define QS_STR 68
#define VS_STR 72
#define QS_FLOATS (64 * QS_STR)
#define KS_FLOATS (64 * QS_STR)
#define VS_FLOATS (64 * VS_STR)
#define PS_FLOATS (64 * QS_STR)
#define ATTN_SMEM_BYTES ((QS_FLOATS + 2*KS_FLOATS + 2*VS_FLOATS + PS_FLOATS) * 4)

__global__ void __launch_bounds__(128) attn_tc_kernel(
    const float* __restrict__ qkv, __half* __restrict__ y)
{
    extern __shared__ float sm[];
    float* Qs = sm;
    float* Ks = Qs + QS_FLOATS;
    float* Vs = Ks + 2 * KS_FLOATS;
    float* Ps = Vs + 2 * VS_FLOATS;

    const int qt   = blockIdx.x;
    const int h    = blockIdx.y;
    const int b    = blockIdx.z;
    const int tid  = threadIdx.x;
    const int lane = tid & 31;
    const int w    = tid >> 5;
    const int fr   = lane >> 2;
    const int fc   = lane & 3;

    const size_t base = (size_t)(b * T_) * (3 * C_) + h * D_;

    {
        #pragma unroll
        for (int i = 0; i < 8; i++) {
            const int idx = i * 128 + tid;
            const int r = idx >> 4, c4 = idx & 15;
            const float* src = qkv + base + (size_t)(qt * 64 + r) * (3 * C_) + c4 * 4;
            cp_async16(Qs + r * QS_STR + c4 * 4, src);
        }
        #pragma unroll
        for (int i = 0; i < 8; i++) {
            const int idx = i * 128 + tid;
            const int r = idx >> 4, c4 = idx & 15;
            const float* src = qkv + base + (size_t)(r) * (3 * C_) + c4 * 4;
            cp_async16(Ks + r * QS_STR + c4 * 4, src + C_);
            cp_async16(Vs + r * VS_STR + c4 * 4, src + 2 * C_);
        }
        cp_commit();
    }

    auto load_kv = [&](int kt, int bufi) {
        float* Kb = Ks + bufi * KS_FLOATS;
        float* Vb = Vs + bufi * VS_FLOATS;
        #pragma unroll
        for (int i = 0; i < 8; i++) {
            const int idx = i * 128 + tid;
            const int r = idx >> 4, c4 = idx & 15;
            const float* src = qkv + base + (size_t)(kt * 64 + r) * (3 * C_) + c4 * 4;
            cp_async16(Kb + r * QS_STR + c4 * 4, src + C_);
            cp_async16(Vb + r * VS_STR + c4 * 4, src + 2 * C_);
        }
        cp_commit();
    };

    float accO[8][4];
    #pragma unroll
    for (int ni = 0; ni < 8; ni++)
        #pragma unroll
        for (int r = 0; r < 4; r++) accO[ni][r] = 0.f;
    float m0 = -INFINITY, m1 = -INFINITY, l0 = 0.f, l1 = 0.f;

    float* Ps_w = Ps + w * 16 * QS_STR;
    const int rlo = w * 16 + fr;

    int buf = 0;
    for (int kt = 0; kt <= qt; kt++) {
        if (kt < qt) { load_kv(kt + 1, buf ^ 1); cp_wait<1>(); }
        else         { cp_wait<0>(); }
        __syncthreads();

        const float* Kb = Ks + buf * KS_FLOATS;
        const float* Vb = Vs + buf * VS_FLOATS;

        float accS[8][4];
        #pragma unroll
        for (int ni = 0; ni < 8; ni++)
            #pragma unroll
            for (int r = 0; r < 4; r++) accS[ni][r] = 0.f;

        #pragma unroll
        for (int kk = 0; kk < 8; kk++) {
            const int kb = kk * 8;
            const uint32_t a0 = __float_as_uint(Qs[(rlo    ) * QS_STR + kb + fc    ]);
            const uint32_t a1 = __float_as_uint(Qs[(rlo + 8) * QS_STR + kb + fc    ]);
            const uint32_t a2 = __float_as_uint(Qs[(rlo    ) * QS_STR + kb + fc + 4]);
            const uint32_t a3 = __float_as_uint(Qs[(rlo + 8) * QS_STR + kb + fc + 4]);
            #pragma unroll
            for (int ni = 0; ni < 8; ni++) {
                const uint32_t b0 = __float_as_uint(Kb[(ni*8 + fr) * QS_STR + kb + fc    ]);
                const uint32_t b1 = __float_as_uint(Kb[(ni*8 + fr) * QS_STR + kb + fc + 4]);
                mma_tf32(accS[ni][0], accS[ni][1], accS[ni][2], accS[ni][3],
                         a0, a1, a2, a3, b0, b1);
            }
        }

        const bool diag = (kt == qt);
        float mx0 = -INFINITY, mx1 = -INFINITY;
        #pragma unroll
        for (int ni = 0; ni < 8; ni++) {
            float s0 = accS[ni][0] * 0.125f;
            float s1 = accS[ni][1] * 0.125f;
            float s2 = accS[ni][2] * 0.125f;
            float s3 = accS[ni][3] * 0.125f;
            if (diag) {
                const int j = ni * 8 + 2 * fc;
                if (j     > rlo    ) s0 = -INFINITY;
                if (j + 1 > rlo    ) s1 = -INFINITY;
                if (j     > rlo + 8) s2 = -INFINITY;
                if (j + 1 > rlo + 8) s3 = -INFINITY;
            }
            accS[ni][0] = s0; accS[ni][1] = s1;
            accS[ni][2] = s2; accS[ni][3] = s3;
            mx0 = fmaxf(mx0, fmaxf(s0, s1));
            mx1 = fmaxf(mx1, fmaxf(s2, s3));
        }
        mx0 = fmaxf(mx0, __shfl_xor_sync(0xffffffffu, mx0, 1));
        mx0 = fmaxf(mx0, __shfl_xor_sync(0xffffffffu, mx0, 2));
        mx1 = fmaxf(mx1, __shfl_xor_sync(0xffffffffu, mx1, 1));
        mx1 = fmaxf(mx1, __shfl_xor_sync(0xffffffffu, mx1, 2));

        const float mn0 = fmaxf(m0, mx0);
        const float mn1 = fmaxf(m1, mx1);
        const float c0 = __expf(m0 - mn0);
        const float c1 = __expf(m1 - mn1);

        float ls0 = 0.f, ls1 = 0.f;
        #pragma unroll
        for (int ni = 0; ni < 8; ni++) {
            const float p0 = __expf(accS[ni][0] - mn0);
            const float p1 = __expf(accS[ni][1] - mn0);
            const float p2 = __expf(accS[ni][2] - mn1);
            const float p3 = __expf(accS[ni][3] - mn1);
            ls0 += p0 + p1;  ls1 += p2 + p3;
            accO[ni][0] *= c0; accO[ni][1] *= c0;
            accO[ni][2] *= c1; accO[ni][3] *= c1;
            const int colp = ni * 8 + 2 * fc;
            Ps_w[(fr    ) * QS_STR + colp    ] = tf32_round(p0);
            Ps_w[(fr    ) * QS_STR + colp + 1] = tf32_round(p1);
            Ps_w[(fr + 8) * QS_STR + colp    ] = tf32_round(p2);
            Ps_w[(fr + 8) * QS_STR + colp + 1] = tf32_round(p3);
        }
        ls0 += __shfl_xor_sync(0xffffffffu, ls0, 1);
        ls0 += __shfl_xor_sync(0xffffffffu, ls0, 2);
        ls1 += __shfl_xor_sync(0xffffffffu, ls1, 1);
        ls1 += __shfl_xor_sync(0xffffffffu, ls1, 2);
        l0 = l0 * c0 + ls0;
        l1 = l1 * c1 + ls1;
        m0 = mn0; m1 = mn1;

        __syncwarp();

        #pragma unroll
        for (int kk = 0; kk < 8; kk++) {
            const int kb = kk * 8;
            const uint32_t a0 = __float_as_uint(Ps_w[(fr    ) * QS_STR + kb + fc    ]);
            const uint32_t a1 = __float_as_uint(Ps_w[(fr + 8) * QS_STR + kb + fc    ]);
            const uint32_t a2 = __float_as_uint(Ps_w[(fr    ) * QS_STR + kb + fc + 4]);
            const uint32_t a3 = __float_as_uint(Ps_w[(fr + 8) * QS_STR + kb + fc + 4]);
            #pragma unroll
            for (int ni = 0; ni < 8; ni++) {
                const uint32_t b0 = __float_as_uint(Vb[(kb + fc    ) * VS_STR + ni*8 + fr]);
                const uint32_t b1 = __float_as_uint(Vb[(kb + fc + 4) * VS_STR + ni*8 + fr]);
                mma_tf32(accO[ni][0], accO[ni][1], accO[ni][2], accO[ni][3],
                         a0, a1, a2, a3, b0, b1);
            }
        }

        __syncthreads();
        buf ^= 1;
    }

    const float inv0 = 1.f / l0;
    const float inv1 = 1.f / l1;
    const size_t grow = (size_t)(b * T_ + qt * 64 + rlo);
    #pragma unroll
    for (int ni = 0; ni < 8; ni++) {
        const int col = h * D_ + ni * 8 + 2 * fc;
        *(__half2*)(y + grow * C_ + col) =
            __halves2half2(__float2half_rn(accO[ni][0] * inv0),
                           __float2half_rn(accO[ni][1] * inv0));
        *(__half2*)(y + (grow + 8) * C_ + col) =
            __halves2half2(__float2half_rn(accO[ni][2] * inv1),
                           __float2half_rn(accO[ni][3] * inv1));
    }
}

// ---------------------------------------------------------------------------
// Launch
// ---------------------------------------------------------------------------
extern "C" void kernel_launch(void* const* d_in, const int* in_sizes, int n_in,
                              void* d_out, int out_size)
{
    (void)in_sizes; (void)n_in; (void)out_size;
    const float* x     = (const float*)d_in[0];
    const float* ln1_w = (const float*)d_in[1];
    const float* ln1_b = (const float*)d_in[2];
    const float* w_qkv = (const float*)d_in[3];
    const float* b_qkv = (const float*)d_in[4];
    const float* w_o   = (const float*)d_in[5];
    const float* b_o   = (const float*)d_in[6];
    const float* ln2_w = (const float*)d_in[7];
    const float* ln2_b = (const float*)d_in[8];
    const float* w_fc  = (const float*)d_in[9];
    const float* b_fc  = (const float*)d_in[10];
    const float* w_out = (const float*)d_in[11];
    const float* b_out = (const float*)d_in[12];
    float* out = (float*)d_out;

    __half *xn, *y, *hbuf, *wq, *wo, *wf, *wu;
    float *qkv, *x1;
    cudaGetSymbolAddress((void**)&xn,   g_xn);
    cudaGetSymbolAddress((void**)&qkv,  g_qkv);
    cudaGetSymbolAddress((void**)&y,    g_y);
    cudaGetSymbolAddress((void**)&x1,   g_x1);
    cudaGetSymbolAddress((void**)&hbuf, g_h);
    cudaGetSymbolAddress((void**)&wq,   g_wqkv);
    cudaGetSymbolAddress((void**)&wo,   g_wo);
    cudaGetSymbolAddress((void**)&wf,   g_wfc);
    cudaGetSymbolAddress((void**)&wu,   g_wout);

    cudaFuncSetAttribute(gemm_h_kernel<0,0,1>,
        cudaFuncAttributeMaxDynamicSharedMemorySize, SMEM_BYTES);
    cudaFuncSetAttribute(gemm_h_kernel<0,1,0>,
        cudaFuncAttributeMaxDynamicSharedMemorySize, SMEM_BYTES);
    cudaFuncSetAttribute(gemm_h_kernel<1,0,2>,
        cudaFuncAttributeMaxDynamicSharedMemorySize, SMEM_BYTES);
    cudaFuncSetAttribute(attn_tc_kernel,
        cudaFuncAttributeMaxDynamicSharedMemorySize, ATTN_SMEM_BYTES);

    // 0) weight prep: fp32 -> fp16 interleaved
    wprep_kernel<<<(C_/2 * (3*C_)/4 + 255)/256, 256>>>(w_qkv, wq, C_, 3*C_);
    wprep_kernel<<<(C_/2 * C_/4      + 255)/256, 256>>>(w_o,   wo, C_, C_);
    wprep_kernel<<<(C_/2 * FF_/4     + 255)/256, 256>>>(w_fc,  wf, C_, FF_);
    wprep_kernel<<<(FF_/2 * C_/4     + 255)/256, 256>>>(w_out, wu, FF_, C_);

    // 1) LN1 -> fp16
    ln_kernel<<<M_, 256>>>(x, ln1_w, ln1_b, xn);
    // 2) qkv = xn @ w_qkv + b_qkv  (fp32 out, tf32-rounded for attention)
    gemm_h_kernel<0,0,1><<<dim3(3 * C_ / BN, M_ / BM), 256, SMEM_BYTES>>>(
        xn, wq, b_qkv, nullptr, qkv, M_, 3 * C_, C_);
    // 3) causal attention -> y (fp16)
    attn_tc_kernel<<<dim3(T_ / 64, H_, B_), 128, ATTN_SMEM_BYTES>>>(qkv, y);
    // 4) x1 = x + y @ w_o + b_o (fp32)
    gemm_h_kernel<0,1,0><<<dim3(C_ / BN, M_ / BM), 256, SMEM_BYTES>>>(
        y, wo, b_o, x, x1, M_, C_, C_);
    // 5) LN2 -> fp16
    ln_kernel<<<M_, 256>>>(x1, ln2_w, ln2_b, xn);
    // 6) h = gelu(xn @ w_fc + b_fc) -> fp16
    gemm_h_kernel<1,0,2><<<dim3(FF_ / BN, M_ / BM), 256, SMEM_BYTES>>>(
        xn, wf, b_fc, nullptr, hbuf, M_, FF_, C_);
    // 7) out = x1 + h @ w_out + b_out (fp32)
    gemm_h_kernel<0,1,0><<<dim3(C_ / BN, M_ / BM), 256, SMEM_BYTES>>>(
        hbuf, wu, b_out, x1, out, M_, C_, FF_);
}

// round 9
// speedup vs baseline: 7.9533x; 1.2010x over previous
#include <cuda_runtime.h>
#include <cuda_fp16.h>
#include <math.h>
#include <stdint.h>

// Problem constants
#define B_  4
#define T_  2048
#define H_  16
#define D_  64
#define C_  1024
#define FF_ 4096
#define M_  (B_ * T_)   // 8192 rows

// ---------------------------------------------------------------------------
// Scratch (device globals — no runtime allocation allowed)
// ---------------------------------------------------------------------------
__device__ __half g_xn  [M_ * C_];        // LN output (fp16, GEMM A-side)
__device__ __half g_qkv [M_ * 3 * C_];    // qkv projections (fp16)
__device__ __half g_y   [M_ * C_];        // attention output (fp16)
__device__ float  g_x1  [M_ * C_];        // first residual (fp32)
__device__ __half g_h   [M_ * FF_];       // gelu(fc) activations (fp16)
// fp16 k-pair-interleaved weights: element (k,n) at  (k>>1)*2N + 2n + (k&1)
__device__ __half g_wqkv[C_ * 3 * C_];
__device__ __half g_wo  [C_ * C_];
__device__ __half g_wfc [C_ * FF_];
__device__ __half g_wout[FF_ * C_];

// ---------------------------------------------------------------------------
// Helpers
// ---------------------------------------------------------------------------
__device__ __forceinline__ uint32_t f2tf32(float f) {
    uint32_t r;
    asm("cvt.rna.tf32.f32 %0, %1;" : "=r"(r) : "f"(f));
    return r;
}
__device__ __forceinline__ float tf32_round(float f) {
    return __uint_as_float(f2tf32(f));
}

__device__ __forceinline__ void mma_f16(
    float& d0, float& d1, float& d2, float& d3,
    uint32_t a0, uint32_t a1, uint32_t a2, uint32_t a3,
    uint32_t b0, uint32_t b1)
{
    asm volatile(
        "mma.sync.aligned.m16n8k16.row.col.f32.f16.f16.f32 "
        "{%0,%1,%2,%3}, {%4,%5,%6,%7}, {%8,%9}, {%0,%1,%2,%3};\n"
        : "+f"(d0), "+f"(d1), "+f"(d2), "+f"(d3)
        : "r"(a0), "r"(a1), "r"(a2), "r"(a3), "r"(b0), "r"(b1));
}

__device__ __forceinline__ void ldmx4t(
    uint32_t& d0, uint32_t& d1, uint32_t& d2, uint32_t& d3, uint32_t addr)
{
    asm volatile(
        "ldmatrix.sync.aligned.m8n8.x4.trans.shared.b16 {%0,%1,%2,%3}, [%4];"
        : "=r"(d0), "=r"(d1), "=r"(d2), "=r"(d3) : "r"(addr));
}

__device__ __forceinline__ void cp_async16(void* dst_smem, const void* src) {
    uint32_t d = (uint32_t)__cvta_generic_to_shared(dst_smem);
    asm volatile("cp.async.cg.shared.global [%0], [%1], 16;\n" :: "r"(d), "l"(src));
}
__device__ __forceinline__ void cp_commit() {
    asm volatile("cp.async.commit_group;\n");
}
template<int N>
__device__ __forceinline__ void cp_wait() {
    asm volatile("cp.async.wait_group %0;\n" :: "n"(N));
}

__device__ __forceinline__ float gelu_exact(float x) {
    return 0.5f * x * (1.0f + erff(x * 0.70710678118654752f));
}

// ---------------------------------------------------------------------------
// Weight prep: fp32 [K][N] -> fp16 k-pair-interleaved [K/2][N][2]
// ---------------------------------------------------------------------------
__global__ void __launch_bounds__(256) wprep_kernel(
    const float* __restrict__ src, __half* __restrict__ dst, int K, int N)
{
    const int total = (K >> 1) * (N >> 2);
    const int idx = blockIdx.x * 256 + threadIdx.x;
    if (idx >= total) return;
    const int nq = N >> 2;
    const int kp = idx / nq;
    const int n4 = idx - kp * nq;
    const float4 r0 = *(const float4*)(src + (size_t)(2 * kp)     * N + 4 * n4);
    const float4 r1 = *(const float4*)(src + (size_t)(2 * kp + 1) * N + 4 * n4);
    __half2* d = (__half2*)(dst + (size_t)kp * (2 * N) + 8 * n4);
    d[0] = __halves2half2(__float2half_rn(r0.x), __float2half_rn(r1.x));
    d[1] = __halves2half2(__float2half_rn(r0.y), __float2half_rn(r1.y));
    d[2] = __halves2half2(__float2half_rn(r0.z), __float2half_rn(r1.z));
    d[3] = __halves2half2(__float2half_rn(r0.w), __float2half_rn(r1.w));
}

// ---------------------------------------------------------------------------
// LayerNorm: outputs fp16 (feeds GEMM A-sides)
// ---------------------------------------------------------------------------
__global__ void __launch_bounds__(256) ln_kernel(
    const float* __restrict__ x, const float* __restrict__ w,
    const float* __restrict__ b, __half* __restrict__ out)
{
    const int row = blockIdx.x;
    const int tid = threadIdx.x;
    const float4 v = ((const float4*)(x + (size_t)row * C_))[tid];

    float s  = v.x + v.y + v.z + v.w;
    float s2 = v.x*v.x + v.y*v.y + v.z*v.z + v.w*v.w;

    #pragma unroll
    for (int o = 16; o > 0; o >>= 1) {
        s  += __shfl_xor_sync(0xffffffffu, s,  o);
        s2 += __shfl_xor_sync(0xffffffffu, s2, o);
    }

    __shared__ float red[18];
    const int warp = tid >> 5, lane = tid & 31;
    if (lane == 0) { red[warp] = s; red[8 + warp] = s2; }
    __syncthreads();
    if (warp == 0) {
        float a  = (lane < 8) ? red[lane]     : 0.f;
        float a2 = (lane < 8) ? red[8 + lane] : 0.f;
        #pragma unroll
        for (int o = 4; o > 0; o >>= 1) {
            a  += __shfl_xor_sync(0xffffffffu, a,  o);
            a2 += __shfl_xor_sync(0xffffffffu, a2, o);
        }
        if (lane == 0) { red[16] = a * (1.0f / C_); red[17] = a2 * (1.0f / C_); }
    }
    __syncthreads();

    const float mean = red[16];
    const float var  = red[17] - mean * mean;
    const float rstd = rsqrtf(var + 1e-5f);

    const float4 wv = ((const float4*)w)[tid];
    const float4 bv = ((const float4*)b)[tid];
    __half2* op = (__half2*)(out + (size_t)row * C_ + 4 * tid);
    op[0] = __halves2half2(__float2half_rn((v.x - mean) * rstd * wv.x + bv.x),
                           __float2half_rn((v.y - mean) * rstd * wv.y + bv.y));
    op[1] = __halves2half2(__float2half_rn((v.z - mean) * rstd * wv.z + bv.z),
                           __float2half_rn((v.w - mean) * rstd * wv.w + bv.w));
}

// ---------------------------------------------------------------------------
// FP16 tensor-core GEMM (proven R7 kernel).
// CTA 128x128x32, 8 warps (2x4) of 64x32, mma.m16n8k16, 3-stage cp.async.
// OUT: 0 = f32, 1 = f32 tf32-rounded, 2 = f16.
// ---------------------------------------------------------------------------
#define BM 128
#define BN 128
#define BK 32
#define STAGES 3
#define A_STR 40
#define B_STR 272
#define A_TILE_H (BM * A_STR)          // 5120 halves
#define B_TILE_H (16 * B_STR)          // 4352 halves
#define SMEM_BYTES (STAGES * (A_TILE_H + B_TILE_H) * 2)   // 56832

template<int ACT, int RES, int OUT>
__global__ void __launch_bounds__(256) gemm_h_kernel(
    const __half* __restrict__ A, const __half* __restrict__ Wp,
    const float* __restrict__ bias, const float* __restrict__ res,
    void* __restrict__ outv, int M, int N, int K)
{
    extern __shared__ __half hsm[];
    __half* As = hsm;
    __half* Bs = hsm + STAGES * A_TILE_H;

    const int tid  = threadIdx.x;
    const int lane = tid & 31;
    const int wid  = tid >> 5;
    const int wm   = wid >> 2;
    const int wn   = wid & 3;
    const int bm   = blockIdx.y;
    const int bn   = blockIdx.x;
    const int fr   = lane >> 2;
    const int fc   = lane & 3;

    float acc[4][4][4];
    #pragma unroll
    for (int i = 0; i < 4; i++)
        #pragma unroll
        for (int j = 0; j < 4; j++)
            #pragma unroll
            for (int r = 0; r < 4; r++) acc[i][j][r] = 0.f;

    const int ntiles = K / BK;

    auto load_tile = [&](int t, int stg) {
        const int k0 = t * BK;
        __half* Ab = As + stg * A_TILE_H;
        __half* Bb = Bs + stg * B_TILE_H;
        #pragma unroll
        for (int i = 0; i < 2; i++) {
            const int idx = i * 256 + tid;
            const int row = idx >> 2, c4 = idx & 3;
            cp_async16(Ab + row * A_STR + c4 * 8,
                       A + (size_t)(bm * BM + row) * K + k0 + c4 * 8);
        }
        const int kp0 = k0 >> 1;
        #pragma unroll
        for (int i = 0; i < 2; i++) {
            const int idx = i * 256 + tid;
            const int kp = idx >> 5, ch = idx & 31;
            cp_async16(Bb + kp * B_STR + ch * 8,
                       Wp + (size_t)(kp0 + kp) * (2 * N) + (size_t)bn * (2 * BN) + ch * 8);
        }
        cp_commit();
    };

    load_tile(0, 0);
    load_tile(1, 1);

    for (int t = 0; t < ntiles; t++) {
        if (t + 2 < ntiles) load_tile(t + 2, (t + 2) % STAGES);
        else                cp_commit();
        cp_wait<2>();
        __syncthreads();

        const __half* Ab = As + (t % STAGES) * A_TILE_H;
        const __half* Bb = Bs + (t % STAGES) * B_TILE_H;

        #pragma unroll
        for (int ks = 0; ks < 2; ks++) {
            const int kc = ks * 16;
            uint32_t af[4][4], bf[4][2];
            #pragma unroll
            for (int mi = 0; mi < 4; mi++) {
                const int base = (wm * 64 + mi * 16 + fr) * A_STR + kc + 2 * fc;
                af[mi][0] = *(const uint32_t*)&Ab[base];
                af[mi][1] = *(const uint32_t*)&Ab[base + 8 * A_STR];
                af[mi][2] = *(const uint32_t*)&Ab[base + 8];
                af[mi][3] = *(const uint32_t*)&Ab[base + 8 * A_STR + 8];
            }
            const int kp = ks * 8 + fc;
            #pragma unroll
            for (int ni = 0; ni < 4; ni++) {
                const int n2 = 2 * (wn * 32 + ni * 8 + fr);
                bf[ni][0] = *(const uint32_t*)&Bb[kp * B_STR + n2];
                bf[ni][1] = *(const uint32_t*)&Bb[(kp + 4) * B_STR + n2];
            }
            #pragma unroll
            for (int mi = 0; mi < 4; mi++)
                #pragma unroll
                for (int ni = 0; ni < 4; ni++)
                    mma_f16(acc[mi][ni][0], acc[mi][ni][1],
                            acc[mi][ni][2], acc[mi][ni][3],
                            af[mi][0], af[mi][1], af[mi][2], af[mi][3],
                            bf[ni][0], bf[ni][1]);
        }
        __syncthreads();
    }

    // ---- epilogue ----
    #pragma unroll
    for (int mi = 0; mi < 4; mi++) {
        const int row0 = bm * BM + wm * 64 + mi * 16 + fr;
        #pragma unroll
        for (int ni = 0; ni < 4; ni++) {
            const int col = bn * BN + wn * 32 + ni * 8 + fc * 2;
            const float b0 = bias[col], b1 = bias[col + 1];

            float v0 = acc[mi][ni][0] + b0;
            float v1 = acc[mi][ni][1] + b1;
            float v2 = acc[mi][ni][2] + b0;
            float v3 = acc[mi][ni][3] + b1;
            if (ACT == 1) {
                v0 = gelu_exact(v0); v1 = gelu_exact(v1);
                v2 = gelu_exact(v2); v3 = gelu_exact(v3);
            }
            if (RES) {
                const float2 r0 = *(const float2*)(res + (size_t)row0 * N + col);
                const float2 r1 = *(const float2*)(res + (size_t)(row0 + 8) * N + col);
                v0 += r0.x; v1 += r0.y; v2 += r1.x; v3 += r1.y;
            }
            if (OUT == 2) {
                __half* out = (__half*)outv;
                *(__half2*)(out + (size_t)row0 * N + col) =
                    __halves2half2(__float2half_rn(v0), __float2half_rn(v1));
                *(__half2*)(out + (size_t)(row0 + 8) * N + col) =
                    __halves2half2(__float2half_rn(v2), __float2half_rn(v3));
            } else {
                if (OUT == 1) {
                    v0 = tf32_round(v0); v1 = tf32_round(v1);
                    v2 = tf32_round(v2); v3 = tf32_round(v3);
                }
                float* out = (float*)outv;
                *(float2*)(out + (size_t)row0 * N + col)       = make_float2(v0, v1);
                *(float2*)(out + (size_t)(row0 + 8) * N + col) = make_float2(v2, v3);
            }
        }
    }
}

// ---------------------------------------------------------------------------
// FP16 tensor-core causal flash attention.
// CTA = 128 threads (4 warps) per (b, h, 64-query tile); warp w owns rows
// [16w,16w+16). K/V double-buffered via cp.async. S and PV use m16n8k16
// (fp32 acc). V consumed through ldmatrix.x4.trans from its natural [j][d]
// layout. All SMEM tiles stride 72 halves (144B): conflict-free.
// ---------------------------------------------------------------------------
#define HS 72
#define QH (64 * HS)
#define ATTN_SMEM_BYTES ((QH * 6) * 2)    // Q + 2K + 2V + P = 55296 B

__global__ void __launch_bounds__(128) attn_h_kernel(
    const __half* __restrict__ qkv, __half* __restrict__ y)
{
    extern __shared__ __half asm_[];
    __half* Qs = asm_;
    __half* Ks = Qs + QH;          // 2 buffers
    __half* Vs = Ks + 2 * QH;      // 2 buffers
    __half* Ps = Vs + 2 * QH;

    const int qt   = blockIdx.x;
    const int h    = blockIdx.y;
    const int b    = blockIdx.z;
    const int tid  = threadIdx.x;
    const int lane = tid & 31;
    const int w    = tid >> 5;
    const int fr   = lane >> 2;
    const int fc   = lane & 3;

    const size_t base = (size_t)(b * T_) * (3 * C_) + h * D_;

    // Q tile + first K/V tile
    {
        #pragma unroll
        for (int i = 0; i < 4; i++) {
            const int idx = i * 128 + tid;     // 0..511
            const int r = idx >> 3, ch = idx & 7;
            cp_async16(Qs + r * HS + ch * 8,
                       qkv + base + (size_t)(qt * 64 + r) * (3 * C_) + ch * 8);
        }
        #pragma unroll
        for (int i = 0; i < 4; i++) {
            const int idx = i * 128 + tid;
            const int r = idx >> 3, ch = idx & 7;
            const __half* src = qkv + base + (size_t)r * (3 * C_) + ch * 8;
            cp_async16(Ks + r * HS + ch * 8, src + C_);
            cp_async16(Vs + r * HS + ch * 8, src + 2 * C_);
        }
        cp_commit();
    }

    auto load_kv = [&](int kt, int bufi) {
        __half* Kb = Ks + bufi * QH;
        __half* Vb = Vs + bufi * QH;
        #pragma unroll
        for (int i = 0; i < 4; i++) {
            const int idx = i * 128 + tid;
            const int r = idx >> 3, ch = idx & 7;
            const __half* src = qkv + base + (size_t)(kt * 64 + r) * (3 * C_) + ch * 8;
            cp_async16(Kb + r * HS + ch * 8, src + C_);
            cp_async16(Vb + r * HS + ch * 8, src + 2 * C_);
        }
        cp_commit();
    };

    float accO[8][4];
    #pragma unroll
    for (int ni = 0; ni < 8; ni++)
        #pragma unroll
        for (int r = 0; r < 4; r++) accO[ni][r] = 0.f;
    float m0 = -INFINITY, m1 = -INFINITY, l0 = 0.f, l1 = 0.f;

    __half* Ps_w = Ps + w * 16 * HS;
    const int rlo = w * 16 + fr;

    int buf = 0;
    for (int kt = 0; kt <= qt; kt++) {
        if (kt < qt) { load_kv(kt + 1, buf ^ 1); cp_wait<1>(); }
        else         { cp_wait<0>(); }
        __syncthreads();

        const __half* Kb = Ks + buf * QH;
        const __half* Vb = Vs + buf * QH;

        // ---- S = Q K^T ----
        float accS[8][4];
        #pragma unroll
        for (int ni = 0; ni < 8; ni++)
            #pragma unroll
            for (int r = 0; r < 4; r++) accS[ni][r] = 0.f;

        #pragma unroll
        for (int ks = 0; ks < 4; ks++) {
            const int kc = ks * 16;
            const uint32_t a0 = *(const uint32_t*)&Qs[(rlo    ) * HS + kc + 2*fc];
            const uint32_t a1 = *(const uint32_t*)&Qs[(rlo + 8) * HS + kc + 2*fc];
            const uint32_t a2 = *(const uint32_t*)&Qs[(rlo    ) * HS + kc + 8 + 2*fc];
            const uint32_t a3 = *(const uint32_t*)&Qs[(rlo + 8) * HS + kc + 8 + 2*fc];
            #pragma unroll
            for (int ni = 0; ni < 8; ni++) {
                const uint32_t b0 = *(const uint32_t*)&Kb[(ni*8 + fr) * HS + kc + 2*fc];
                const uint32_t b1 = *(const uint32_t*)&Kb[(ni*8 + fr) * HS + kc + 8 + 2*fc];
                mma_f16(accS[ni][0], accS[ni][1], accS[ni][2], accS[ni][3],
                        a0, a1, a2, a3, b0, b1);
            }
        }

        // ---- scale + mask + online softmax ----
        const bool diag = (kt == qt);
        float mx0 = -INFINITY, mx1 = -INFINITY;
        #pragma unroll
        for (int ni = 0; ni < 8; ni++) {
            float s0 = accS[ni][0] * 0.125f;
            float s1 = accS[ni][1] * 0.125f;
            float s2 = accS[ni][2] * 0.125f;
            float s3 = accS[ni][3] * 0.125f;
            if (diag) {
                const int j = ni * 8 + 2 * fc;
                if (j     > rlo    ) s0 = -INFINITY;
                if (j + 1 > rlo    ) s1 = -INFINITY;
                if (j     > rlo + 8) s2 = -INFINITY;
                if (j + 1 > rlo + 8) s3 = -INFINITY;
            }
            accS[ni][0] = s0; accS[ni][1] = s1;
            accS[ni][2] = s2; accS[ni][3] = s3;
            mx0 = fmaxf(mx0, fmaxf(s0, s1));
            mx1 = fmaxf(mx1, fmaxf(s2, s3));
        }
        mx0 = fmaxf(mx0, __shfl_xor_sync(0xffffffffu, mx0, 1));
        mx0 = fmaxf(mx0, __shfl_xor_sync(0xffffffffu, mx0, 2));
        mx1 = fmaxf(mx1, __shfl_xor_sync(0xffffffffu, mx1, 1));
        mx1 = fmaxf(mx1, __shfl_xor_sync(0xffffffffu, mx1, 2));

        const float mn0 = fmaxf(m0, mx0);
        const float mn1 = fmaxf(m1, mx1);
        const float c0 = __expf(m0 - mn0);
        const float c1 = __expf(m1 - mn1);

        float ls0 = 0.f, ls1 = 0.f;
        #pragma unroll
        for (int ni = 0; ni < 8; ni++) {
            const float p0 = __expf(accS[ni][0] - mn0);
            const float p1 = __expf(accS[ni][1] - mn0);
            const float p2 = __expf(accS[ni][2] - mn1);
            const float p3 = __expf(accS[ni][3] - mn1);
            ls0 += p0 + p1;  ls1 += p2 + p3;
            accO[ni][0] *= c0; accO[ni][1] *= c0;
            accO[ni][2] *= c1; accO[ni][3] *= c1;
            const int colp = ni * 8 + 2 * fc;
            *(__half2*)&Ps_w[(fr    ) * HS + colp] =
                __halves2half2(__float2half_rn(p0), __float2half_rn(p1));
            *(__half2*)&Ps_w[(fr + 8) * HS + colp] =
                __halves2half2(__float2half_rn(p2), __float2half_rn(p3));
        }
        ls0 += __shfl_xor_sync(0xffffffffu, ls0, 1);
        ls0 += __shfl_xor_sync(0xffffffffu, ls0, 2);
        ls1 += __shfl_xor_sync(0xffffffffu, ls1, 1);
        ls1 += __shfl_xor_sync(0xffffffffu, ls1, 2);
        l0 = l0 * c0 + ls0;
        l1 = l1 * c1 + ls1;
        m0 = mn0; m1 = mn1;

        __syncwarp();

        // ---- O += P V  (V via ldmatrix.trans from [j][d] layout) ----
        const uint32_t vbase = (uint32_t)__cvta_generic_to_shared(Vb);
        const int mat = lane >> 3, rin = lane & 7;
        #pragma unroll
        for (int ks = 0; ks < 4; ks++) {
            const int kc = ks * 16;
            const uint32_t a0 = *(const uint32_t*)&Ps_w[(fr    ) * HS + kc + 2*fc];
            const uint32_t a1 = *(const uint32_t*)&Ps_w[(fr + 8) * HS + kc + 2*fc];
            const uint32_t a2 = *(const uint32_t*)&Ps_w[(fr    ) * HS + kc + 8 + 2*fc];
            const uint32_t a3 = *(const uint32_t*)&Ps_w[(fr + 8) * HS + kc + 8 + 2*fc];
            #pragma unroll
            for (int np = 0; np < 4; np++) {
                const int ni  = 2 * np;
                const int row = kc + ((mat & 1) ? 8 : 0) + rin;
                const int col = ni * 8 + ((mat & 2) ? 8 : 0);
                uint32_t b0, b1, b2, b3;
                ldmx4t(b0, b1, b2, b3, vbase + (uint32_t)(row * HS + col) * 2);
                mma_f16(accO[ni][0], accO[ni][1], accO[ni][2], accO[ni][3],
                        a0, a1, a2, a3, b0, b1);
                mma_f16(accO[ni+1][0], accO[ni+1][1], accO[ni+1][2], accO[ni+1][3],
                        a0, a1, a2, a3, b2, b3);
            }
        }

        __syncthreads();
        buf ^= 1;
    }

    // ---- epilogue ----
    const float inv0 = 1.f / l0;
    const float inv1 = 1.f / l1;
    const size_t grow = (size_t)(b * T_ + qt * 64 + rlo);
    #pragma unroll
    for (int ni = 0; ni < 8; ni++) {
        const int col = h * D_ + ni * 8 + 2 * fc;
        *(__half2*)(y + grow * C_ + col) =
            __halves2half2(__float2half_rn(accO[ni][0] * inv0),
                           __float2half_rn(accO[ni][1] * inv0));
        *(__half2*)(y + (grow + 8) * C_ + col) =
            __halves2half2(__float2half_rn(accO[ni][2] * inv1),
                           __float2half_rn(accO[ni][3] * inv1));
    }
}

// ---------------------------------------------------------------------------
// Launch
// ---------------------------------------------------------------------------
extern "C" void kernel_launch(void* const* d_in, const int* in_sizes, int n_in,
                              void* d_out, int out_size)
{
    (void)in_sizes; (void)n_in; (void)out_size;
    const float* x     = (const float*)d_in[0];
    const float* ln1_w = (const float*)d_in[1];
    const float* ln1_b = (const float*)d_in[2];
    const float* w_qkv = (const float*)d_in[3];
    const float* b_qkv = (const float*)d_in[4];
    const float* w_o   = (const float*)d_in[5];
    const float* b_o   = (const float*)d_in[6];
    const float* ln2_w = (const float*)d_in[7];
    const float* ln2_b = (const float*)d_in[8];
    const float* w_fc  = (const float*)d_in[9];
    const float* b_fc  = (const float*)d_in[10];
    const float* w_out = (const float*)d_in[11];
    const float* b_out = (const float*)d_in[12];
    float* out = (float*)d_out;

    __half *xn, *qkv, *y, *hbuf, *wq, *wo, *wf, *wu;
    float *x1;
    cudaGetSymbolAddress((void**)&xn,   g_xn);
    cudaGetSymbolAddress((void**)&qkv,  g_qkv);
    cudaGetSymbolAddress((void**)&y,    g_y);
    cudaGetSymbolAddress((void**)&x1,   g_x1);
    cudaGetSymbolAddress((void**)&hbuf, g_h);
    cudaGetSymbolAddress((void**)&wq,   g_wqkv);
    cudaGetSymbolAddress((void**)&wo,   g_wo);
    cudaGetSymbolAddress((void**)&wf,   g_wfc);
    cudaGetSymbolAddress((void**)&wu,   g_wout);

    cudaFuncSetAttribute(gemm_h_kernel<0,0,2>,
        cudaFuncAttributeMaxDynamicSharedMemorySize, SMEM_BYTES);
    cudaFuncSetAttribute(gemm_h_kernel<0,1,0>,
        cudaFuncAttributeMaxDynamicSharedMemorySize, SMEM_BYTES);
    cudaFuncSetAttribute(gemm_h_kernel<1,0,2>,
        cudaFuncAttributeMaxDynamicSharedMemorySize, SMEM_BYTES);
    cudaFuncSetAttribute(attn_h_kernel,
        cudaFuncAttributeMaxDynamicSharedMemorySize, ATTN_SMEM_BYTES);

    // 0) weight prep: fp32 -> fp16 interleaved
    wprep_kernel<<<(C_/2 * (3*C_)/4 + 255)/256, 256>>>(w_qkv, wq, C_, 3*C_);
    wprep_kernel<<<(C_/2 * C_/4      + 255)/256, 256>>>(w_o,   wo, C_, C_);
    wprep_kernel<<<(C_/2 * FF_/4     + 255)/256, 256>>>(w_fc,  wf, C_, FF_);
    wprep_kernel<<<(FF_/2 * C_/4     + 255)/256, 256>>>(w_out, wu, FF_, C_);

    // 1) LN1 -> fp16
    ln_kernel<<<M_, 256>>>(x, ln1_w, ln1_b, xn);
    // 2) qkv = xn @ w_qkv + b_qkv  -> fp16
    gemm_h_kernel<0,0,2><<<dim3(3 * C_ / BN, M_ / BM), 256, SMEM_BYTES>>>(
        xn, wq, b_qkv, nullptr, qkv, M_, 3 * C_, C_);
    // 3) causal attention (fp16) -> y (fp16)
    attn_h_kernel<<<dim3(T_ / 64, H_, B_), 128, ATTN_SMEM_BYTES>>>(qkv, y);
    // 4) x1 = x + y @ w_o + b_o (fp32)
    gemm_h_kernel<0,1,0><<<dim3(C_ / BN, M_ / BM), 256, SMEM_BYTES>>>(
        y, wo, b_o, x, x1, M_, C_, C_);
    // 5) LN2 -> fp16
    ln_kernel<<<M_, 256>>>(x1, ln2_w, ln2_b, xn);
    // 6) h = gelu(xn @ w_fc + b_fc) -> fp16
    gemm_h_kernel<1,0,2><<<dim3(FF_ / BN, M_ / BM), 256, SMEM_BYTES>>>(
        xn, wf, b_fc, nullptr, hbuf, M_, FF_, C_);
    // 7) out = x1 + h @ w_out + b_out (fp32)
    gemm_h_kernel<0,1,0><<<dim3(C_ / BN, M_ / BM), 256, SMEM_BYTES>>>(
        hbuf, wu, b_out, x1, out, M_, C_, FF_);
}